// round 7
// baseline (speedup 1.0000x reference)
#include <cuda_runtime.h>
#include <stdint.h>

typedef unsigned long long u64;
typedef unsigned int u32;

// ---------------- constant-memory weights ----------------
__constant__ __align__(16) float cW1[64 * 64];   // [k][j] j contiguous
__constant__ __align__(16) float cW2[64 * 16];
__constant__ __align__(16) float cW3[16 * 8];
__constant__ __align__(16) float cW4[8 * 3];
__constant__ __align__(16) float cB1[64];
__constant__ __align__(16) float cB2[16];
__constant__ __align__(16) float cB3[8];
__constant__ __align__(16) float cB4[3];
__constant__ __align__(16) float cEnc[27];

// ---------------- helpers ----------------
static __device__ __forceinline__ u64 pack2(float lo, float hi) {
    u64 r; asm("mov.b64 %0, {%1, %2};" : "=l"(r) : "f"(lo), "f"(hi)); return r;
}
static __device__ __forceinline__ float2 unpack2(u64 v) {
    float2 f; asm("mov.b64 {%0, %1}, %2;" : "=f"(f.x), "=f"(f.y) : "l"(v)); return f;
}
static __device__ __forceinline__ void fma2(u64 &d, u64 a, u64 b) {
    asm("fma.rn.f32x2 %0, %1, %2, %0;" : "+l"(d) : "l"(a), "l"(b));
}
static __device__ __forceinline__ float leaky(float x) { return fmaxf(x, 0.01f * x); }
static __device__ __forceinline__ float sigmoidf(float x) { return 1.0f / (1.0f + __expf(-x)); }
static __device__ __forceinline__ float tanh_fast(float x) {
    return fmaf(2.0f, sigmoidf(2.0f * x), -1.0f);
}

static __device__ __forceinline__ void encode(float i0, float i1, float &x, float &y) {
    float h[4];
#pragma unroll
    for (int j = 0; j < 4; j++)
        h[j] = tanh_fast(fmaf(i0, cEnc[j], fmaf(i1, cEnc[4 + j], cEnc[8 + j])));
    float z0 = cEnc[24], z1 = cEnc[25];
#pragma unroll
    for (int j = 0; j < 4; j++) {
        z0 = fmaf(h[j], cEnc[12 + j * 3 + 0], z0);
        z1 = fmaf(h[j], cEnc[12 + j * 3 + 1], z1);
    }
    x = sigmoidf(z0) * 255.0f;
    y = sigmoidf(z1) * 255.0f;
}

// FC3 (16->8) + FC4 (8->3) + sigmoid*255 (const; tiny traffic)
static __device__ __forceinline__ float3 head(const float *a2) {
    u64 h3[4];
#pragma unroll
    for (int q = 0; q < 4; q++) h3[q] = pack2(cB3[2 * q], cB3[2 * q + 1]);
#pragma unroll
    for (int j = 0; j < 16; j++) {
        float a = a2[j];
        u64 av = pack2(a, a);
        const ulonglong2 *w = (const ulonglong2 *)(cW3 + j * 8);
#pragma unroll
        for (int q = 0; q < 2; q++) {
            ulonglong2 wq = w[q];
            fma2(h3[2 * q], av, wq.x);
            fma2(h3[2 * q + 1], av, wq.y);
        }
    }
    float o0 = cB4[0], o1 = cB4[1], o2 = cB4[2];
#pragma unroll
    for (int q = 0; q < 4; q++) {
        float2 v = unpack2(h3[q]);
        float a0 = leaky(v.x), a1 = leaky(v.y);
        int i0 = 2 * q, i1 = 2 * q + 1;
        o0 = fmaf(a0, cW4[i0 * 3 + 0], o0);
        o1 = fmaf(a0, cW4[i0 * 3 + 1], o1);
        o2 = fmaf(a0, cW4[i0 * 3 + 2], o2);
        o0 = fmaf(a1, cW4[i1 * 3 + 0], o0);
        o1 = fmaf(a1, cW4[i1 * 3 + 1], o1);
        o2 = fmaf(a1, cW4[i1 * 3 + 2], o2);
    }
    float3 r;
    r.x = sigmoidf(leaky(o0)) * 255.0f;
    r.y = sigmoidf(leaky(o1)) * 255.0f;
    r.z = sigmoidf(leaky(o2)) * 255.0f;
    return r;
}

#define MSTRIDE 9   // meta row stride in u64 (72B: conflict-free reads, 2-way STS)
#define KSTRIDE 65  // stage k-row stride in floats (65 == 1 mod 32: conflict-free)
#define META_BYTES (4 * 64 * MSTRIDE * 8)             // 18432
#define STAGE_FLOATS_PER_WARP (64 * KSTRIDE)          // 4160
#define DYN_BYTES (META_BYTES + 4 * STAGE_FLOATS_PER_WARP * 4)  // 18432+66560=84992

// ---------------- kernel: 2 points/thread, warp-coop gather, k-major stage ----------------
__global__ void __launch_bounds__(128, 2) gridnet_2pt(
    const float *__restrict__ pos, const float *__restrict__ dir,
    const float *__restrict__ pos_grid, const float *__restrict__ dir_grid,
    float *__restrict__ out, int n)
{
    extern __shared__ char dynraw[];
    u64 *meta = (u64 *)dynraw;                                // [4][64][MSTRIDE]
    float *stg = (float *)(dynraw + META_BYTES);              // [4][64*KSTRIDE]

    const int tid = threadIdx.x;
    const int warp = tid >> 5, lane = tid & 31;
    const int grp = lane >> 3, f = lane & 7;
    const int wbase = blockIdx.x * 256 + warp * 64;

    u64 *mw = meta + warp * 64 * MSTRIDE;
    float *st = stg + warp * STAGE_FLOATS_PER_WARP;

    // ---- owner: encode both points, write corner metadata (rows lane, lane+32)
#pragma unroll
    for (int pt = 0; pt < 2; pt++) {
        const int row = lane + 32 * pt;
        const int pc = min(wbase + row, n - 1);
        float gx[2], gy[2];
        float a0 = pos[2 * pc], a1 = pos[2 * pc + 1];
        float e0 = dir[2 * pc], e1 = dir[2 * pc + 1];
        encode(a0, a1, gx[0], gy[0]);
        encode(e0, e1, gx[1], gy[1]);
#pragma unroll
        for (int g = 0; g < 2; g++) {
            float x = gx[g], y = gy[g];
            int x0 = min((int)x, 255), y0 = min((int)y, 255);
            float xf = x - (float)x0, yf = y - (float)y0;
            int x1 = min(x0 + 1, 255), y1 = min(y0 + 1, 255);
            u32 o0 = (u32)(y0 * 256 + x0) * 128u;
            u32 o1 = (u32)(y0 * 256 + x1) * 128u;
            u32 o2 = (u32)(y1 * 256 + x0) * 128u;
            u32 o3 = (u32)(y1 * 256 + x1) * 128u;
            float w0 = (1.0f - xf) * (1.0f - yf);
            float w1 = xf * (1.0f - yf);
            float w2 = (1.0f - xf) * yf;
            float w3 = xf * yf;
            u64 *mrow = mw + row * MSTRIDE + g * 4;
            mrow[0] = (u64)o0 | ((u64)__float_as_uint(w0) << 32);
            mrow[1] = (u64)o1 | ((u64)__float_as_uint(w1) << 32);
            mrow[2] = (u64)o2 | ((u64)__float_as_uint(w2) << 32);
            mrow[3] = (u64)o3 | ((u64)__float_as_uint(w3) << 32);
        }
    }
    __syncwarp();

    // ---- loader: 8 lanes per row, blend 4 corners in regs, store k-major
#pragma unroll 1
    for (int g = 0; g < 2; g++) {
        const float *gbase = (g == 0) ? pos_grid : dir_grid;
#pragma unroll
        for (int i = 0; i < 16; i++) {
            int row = i * 4 + grp;
            const u64 *m = mw + row * MSTRIDE + g * 4;
            u64 acc01 = 0, acc23 = 0;
#pragma unroll
            for (int c = 0; c < 4; c++) {
                u64 mwv = m[c];
                u32 off = (u32)mwv;
                float w = __uint_as_float((u32)(mwv >> 32));
                float4 v = __ldg((const float4 *)((const char *)gbase + off) + f);
                u64 wv = pack2(w, w);
                fma2(acc01, wv, pack2(v.x, v.y));
                fma2(acc23, wv, pack2(v.z, v.w));
            }
            float2 lo = unpack2(acc01), hi = unpack2(acc23);
            int kb = g * 32 + 4 * f;
            st[(kb + 0) * KSTRIDE + row] = lo.x;
            st[(kb + 1) * KSTRIDE + row] = lo.y;
            st[(kb + 2) * KSTRIDE + row] = hi.x;
            st[(kb + 3) * KSTRIDE + row] = hi.y;
        }
    }
    __syncwarp();

    // ---- FC1: both points share each weight LDC (64 outs = 32 packed each)
    u64 h1A[32], h1B[32];
#pragma unroll
    for (int q = 0; q < 32; q++) {
        u64 b = pack2(cB1[2 * q], cB1[2 * q + 1]);
        h1A[q] = b;
        h1B[q] = b;
    }
#pragma unroll 8
    for (int k = 0; k < 64; k++) {
        float fa = st[k * KSTRIDE + lane];
        float fb = st[k * KSTRIDE + lane + 32];
        u64 fav = pack2(fa, fa), fbv = pack2(fb, fb);
        const ulonglong2 *w = (const ulonglong2 *)(cW1 + k * 64);
#pragma unroll
        for (int q = 0; q < 16; q++) {
            ulonglong2 wq = w[q];
            fma2(h1A[2 * q], fav, wq.x);
            fma2(h1A[2 * q + 1], fav, wq.y);
            fma2(h1B[2 * q], fbv, wq.x);
            fma2(h1B[2 * q + 1], fbv, wq.y);
        }
    }

    // ---- FC2: 64 -> 16, both points share LDC
    u64 h2A[8], h2B[8];
#pragma unroll
    for (int q = 0; q < 8; q++) {
        u64 b = pack2(cB2[2 * q], cB2[2 * q + 1]);
        h2A[q] = b;
        h2B[q] = b;
    }
#pragma unroll 8
    for (int q = 0; q < 32; q++) {
        float2 vA = unpack2(h1A[q]);
        float2 vB = unpack2(h1B[q]);
        float aA0 = leaky(vA.x), aA1 = leaky(vA.y);
        float aB0 = leaky(vB.x), aB1 = leaky(vB.y);
        u64 aA0v = pack2(aA0, aA0), aA1v = pack2(aA1, aA1);
        u64 aB0v = pack2(aB0, aB0), aB1v = pack2(aB1, aB1);
        const ulonglong2 *w0 = (const ulonglong2 *)(cW2 + (2 * q) * 16);
        const ulonglong2 *w1 = (const ulonglong2 *)(cW2 + (2 * q + 1) * 16);
#pragma unroll
        for (int r = 0; r < 4; r++) {
            ulonglong2 wa = w0[r];
            fma2(h2A[2 * r], aA0v, wa.x);
            fma2(h2A[2 * r + 1], aA0v, wa.y);
            fma2(h2B[2 * r], aB0v, wa.x);
            fma2(h2B[2 * r + 1], aB0v, wa.y);
            ulonglong2 wb = w1[r];
            fma2(h2A[2 * r], aA1v, wb.x);
            fma2(h2A[2 * r + 1], aA1v, wb.y);
            fma2(h2B[2 * r], aB1v, wb.x);
            fma2(h2B[2 * r + 1], aB1v, wb.y);
        }
    }

    // ---- heads + stores
    {
        float a2[16];
#pragma unroll
        for (int q = 0; q < 8; q++) {
            float2 v = unpack2(h2A[q]);
            a2[2 * q] = leaky(v.x);
            a2[2 * q + 1] = leaky(v.y);
        }
        float3 o = head(a2);
        int p = wbase + lane;
        if (p < n) {
            out[p * 3 + 0] = o.x;
            out[p * 3 + 1] = o.y;
            out[p * 3 + 2] = o.z;
        }
    }
    {
        float a2[16];
#pragma unroll
        for (int q = 0; q < 8; q++) {
            float2 v = unpack2(h2B[q]);
            a2[2 * q] = leaky(v.x);
            a2[2 * q + 1] = leaky(v.y);
        }
        float3 o = head(a2);
        int p = wbase + lane + 32;
        if (p < n) {
            out[p * 3 + 0] = o.x;
            out[p * 3 + 1] = o.y;
            out[p * 3 + 2] = o.z;
        }
    }
}

extern "C" void kernel_launch(void *const *d_in, const int *in_sizes, int n_in,
                              void *d_out, int out_size)
{
    const float *pos = (const float *)d_in[0];
    const float *dir = (const float *)d_in[1];
    const float *pos_grid = (const float *)d_in[2];
    const float *dir_grid = (const float *)d_in[3];

    cudaMemcpyToSymbolAsync(cEnc, d_in[4], 8 * sizeof(float), 0, cudaMemcpyDeviceToDevice, 0);
    cudaMemcpyToSymbolAsync(cEnc, d_in[5], 4 * sizeof(float), 8 * sizeof(float), cudaMemcpyDeviceToDevice, 0);
    cudaMemcpyToSymbolAsync(cEnc, d_in[6], 12 * sizeof(float), 12 * sizeof(float), cudaMemcpyDeviceToDevice, 0);
    cudaMemcpyToSymbolAsync(cEnc, d_in[7], 3 * sizeof(float), 24 * sizeof(float), cudaMemcpyDeviceToDevice, 0);
    cudaMemcpyToSymbolAsync(cW1, d_in[8], 64 * 64 * sizeof(float), 0, cudaMemcpyDeviceToDevice, 0);
    cudaMemcpyToSymbolAsync(cB1, d_in[9], 64 * sizeof(float), 0, cudaMemcpyDeviceToDevice, 0);
    cudaMemcpyToSymbolAsync(cW2, d_in[10], 64 * 16 * sizeof(float), 0, cudaMemcpyDeviceToDevice, 0);
    cudaMemcpyToSymbolAsync(cB2, d_in[11], 16 * sizeof(float), 0, cudaMemcpyDeviceToDevice, 0);
    cudaMemcpyToSymbolAsync(cW3, d_in[12], 16 * 8 * sizeof(float), 0, cudaMemcpyDeviceToDevice, 0);
    cudaMemcpyToSymbolAsync(cB3, d_in[13], 8 * sizeof(float), 0, cudaMemcpyDeviceToDevice, 0);
    cudaMemcpyToSymbolAsync(cW4, d_in[14], 8 * 3 * sizeof(float), 0, cudaMemcpyDeviceToDevice, 0);
    cudaMemcpyToSymbolAsync(cB4, d_in[15], 3 * sizeof(float), 0, cudaMemcpyDeviceToDevice, 0);

    cudaFuncSetAttribute(gridnet_2pt, cudaFuncAttributeMaxDynamicSharedMemorySize, DYN_BYTES);

    float *out = (float *)d_out;
    int n = in_sizes[0] / 2;
    int blocks = (n + 255) / 256;
    gridnet_2pt<<<blocks, 128, DYN_BYTES>>>(pos, dir, pos_grid, dir_grid, out, n);
}

// round 8
// speedup vs baseline: 2.7888x; 2.7888x over previous
#include <cuda_runtime.h>
#include <stdint.h>

typedef unsigned long long u64;
typedef unsigned int u32;

// ---------------- small constants kept in cmem (uniform access only) ----------------
__constant__ __align__(16) float cW4[8 * 3];
__constant__ __align__(16) float cB3[8];
__constant__ __align__(16) float cB4[3];
__constant__ __align__(16) float cEnc[27];

// ---------------- smem layout (floats unless noted) ----------------
#define PAD_A 68   // A-stage row pad: banks 4r+c conflict-free
#define PAD_W1 72  // W1 pad: banks 8c+n conflict-free
#define PAD_W2 24
#define OFF_W1 0                       // 64*72 = 4608
#define OFF_W2 4608                    // 64*24 = 1536
#define OFF_W3 6144                    // 128
#define OFF_B1 6272                    // 64
#define OFF_B2 6336                    // 16
#define OFF_STAGE 6352                 // 4 warps * 32*68 = 8704
#define STAGE_PER_WARP (32 * PAD_A)
#define META_BYTE_OFF ((OFF_STAGE + 4 * STAGE_PER_WARP) * 4)  // 60224
#define DYN_BYTES (META_BYTE_OFF + 4 * 32 * 8 * 8)            // + 8192 = 68416

// ---------------- helpers ----------------
static __device__ __forceinline__ u64 pack2(float lo, float hi) {
    u64 r; asm("mov.b64 %0, {%1, %2};" : "=l"(r) : "f"(lo), "f"(hi)); return r;
}
static __device__ __forceinline__ float2 unpack2(u64 v) {
    float2 f; asm("mov.b64 {%0, %1}, %2;" : "=f"(f.x), "=f"(f.y) : "l"(v)); return f;
}
static __device__ __forceinline__ void fma2(u64 &d, u64 a, u64 b) {
    asm("fma.rn.f32x2 %0, %1, %2, %0;" : "+l"(d) : "l"(a), "l"(b));
}
static __device__ __forceinline__ u32 tf32(float x) {
    u32 r; asm("cvt.rna.tf32.f32 %0, %1;" : "=r"(r) : "f"(x)); return r;
}
static __device__ __forceinline__ void mma8(float *d, u32 a0, u32 a1, u32 a2, u32 a3,
                                            u32 b0, u32 b1) {
    asm("mma.sync.aligned.m16n8k8.row.col.f32.tf32.tf32.f32 "
        "{%0,%1,%2,%3},{%4,%5,%6,%7},{%8,%9},{%0,%1,%2,%3};"
        : "+f"(d[0]), "+f"(d[1]), "+f"(d[2]), "+f"(d[3])
        : "r"(a0), "r"(a1), "r"(a2), "r"(a3), "r"(b0), "r"(b1));
}
static __device__ __forceinline__ float leaky(float x) { return fmaxf(x, 0.01f * x); }
static __device__ __forceinline__ float sigmoidf(float x) { return 1.0f / (1.0f + __expf(-x)); }
static __device__ __forceinline__ float tanh_fast(float x) {
    return fmaf(2.0f, sigmoidf(2.0f * x), -1.0f);
}

static __device__ __forceinline__ void encode(float i0, float i1, float &x, float &y) {
    float h[4];
#pragma unroll
    for (int j = 0; j < 4; j++)
        h[j] = tanh_fast(fmaf(i0, cEnc[j], fmaf(i1, cEnc[4 + j], cEnc[8 + j])));
    float z0 = cEnc[24], z1 = cEnc[25];
#pragma unroll
    for (int j = 0; j < 4; j++) {
        z0 = fmaf(h[j], cEnc[12 + j * 3 + 0], z0);
        z1 = fmaf(h[j], cEnc[12 + j * 3 + 1], z1);
    }
    x = sigmoidf(z0) * 255.0f;
    y = sigmoidf(z1) * 255.0f;
}

// ---------------- kernel ----------------
__global__ void __launch_bounds__(128, 3) gridnet_hmma(
    const float *__restrict__ pos, const float *__restrict__ dir,
    const float *__restrict__ pos_grid, const float *__restrict__ dir_grid,
    const float *__restrict__ fc_w1, const float *__restrict__ fc_b1,
    const float *__restrict__ fc_w2, const float *__restrict__ fc_b2,
    const float *__restrict__ fc_w3,
    float *__restrict__ out, int n, int ntiles)
{
    extern __shared__ __align__(16) char smraw[];
    float *smf = (float *)smraw;
    u32 *smu = (u32 *)smraw;

    const int tid = threadIdx.x;
    const int warp = tid >> 5, lane = tid & 31;
    const int grp = lane >> 3, f = lane & 7;   // loader roles
    const int r = lane >> 2, c = lane & 3;     // mma fragment roles

    // ---- stage weights once per CTA (tf32 for W1/W2, fp32 for the rest)
    for (int i = tid; i < 4096; i += 128) {
        int k = i >> 6, nn = i & 63;
        smu[OFF_W1 + k * PAD_W1 + nn] = tf32(fc_w1[i]);
    }
    for (int i = tid; i < 1024; i += 128) {
        int k = i >> 4, nn = i & 15;
        smu[OFF_W2 + k * PAD_W2 + nn] = tf32(fc_w2[i]);
    }
    if (tid < 128) smf[OFF_W3 + tid] = fc_w3[tid];
    if (tid < 64) smf[OFF_B1 + tid] = fc_b1[tid];
    if (tid < 16) smf[OFF_B2 + tid] = fc_b2[tid];
    __syncthreads();

    u32 *stu = smu + OFF_STAGE + warp * STAGE_PER_WARP;
    float *stf = (float *)stu;
    u64 *mw = (u64 *)(smraw + META_BYTE_OFF) + warp * 32 * 8;

    for (int tile = blockIdx.x; tile < ntiles; tile += gridDim.x) {
        const int wbase = tile * 128 + warp * 32;
        const int p = wbase + lane;
        const int pc = min(p, n - 1);

        // ===== owner: encode -> corner metadata =====
        {
            float gx[2], gy[2];
            float a0 = pos[2 * pc], a1 = pos[2 * pc + 1];
            float e0 = dir[2 * pc], e1 = dir[2 * pc + 1];
            encode(a0, a1, gx[0], gy[0]);
            encode(e0, e1, gx[1], gy[1]);
#pragma unroll
            for (int g = 0; g < 2; g++) {
                float x = gx[g], y = gy[g];
                int x0 = min((int)x, 255), y0 = min((int)y, 255);
                float xf = x - (float)x0, yf = y - (float)y0;
                int x1 = min(x0 + 1, 255), y1 = min(y0 + 1, 255);
                u32 o0 = (u32)(y0 * 256 + x0) * 128u;
                u32 o1 = (u32)(y0 * 256 + x1) * 128u;
                u32 o2 = (u32)(y1 * 256 + x0) * 128u;
                u32 o3 = (u32)(y1 * 256 + x1) * 128u;
                float w0 = (1.0f - xf) * (1.0f - yf);
                float w1 = xf * (1.0f - yf);
                float w2 = (1.0f - xf) * yf;
                float w3 = xf * yf;
                u64 *mrow = mw + lane * 8 + g * 4;
                mrow[0] = (u64)o0 | ((u64)__float_as_uint(w0) << 32);
                mrow[1] = (u64)o1 | ((u64)__float_as_uint(w1) << 32);
                mrow[2] = (u64)o2 | ((u64)__float_as_uint(w2) << 32);
                mrow[3] = (u64)o3 | ((u64)__float_as_uint(w3) << 32);
            }
        }
        __syncwarp();

        // ===== loader: coop gather + blend -> tf32 feature stage [32][PAD_A] =====
#pragma unroll 1
        for (int g = 0; g < 2; g++) {
            const float *gbase = (g == 0) ? pos_grid : dir_grid;
#pragma unroll
            for (int i = 0; i < 8; i++) {
                int row = i * 4 + grp;
                const u64 *m = mw + row * 8 + g * 4;
                u64 acc01 = 0, acc23 = 0;
#pragma unroll
                for (int cc = 0; cc < 4; cc++) {
                    u64 mwv = m[cc];
                    u32 off = (u32)mwv;
                    float w = __uint_as_float((u32)(mwv >> 32));
                    float4 v = __ldg((const float4 *)((const char *)gbase + off) + f);
                    u64 wv = pack2(w, w);
                    fma2(acc01, wv, pack2(v.x, v.y));
                    fma2(acc23, wv, pack2(v.z, v.w));
                }
                float2 lo = unpack2(acc01), hi = unpack2(acc23);
                int kb = g * 32 + 4 * f;
                stu[row * PAD_A + kb + 0] = tf32(lo.x);
                stu[row * PAD_A + kb + 1] = tf32(lo.y);
                stu[row * PAD_A + kb + 2] = tf32(hi.x);
                stu[row * PAD_A + kb + 3] = tf32(hi.y);
            }
        }
        __syncwarp();

        // ===== FC1: D[32x64] = X[32x64] @ W1[64x64] via HMMA tf32 =====
        float d1[64];
#pragma unroll
        for (int q = 0; q < 64; q++) d1[q] = 0.0f;
#pragma unroll
        for (int kt = 0; kt < 8; kt++) {
            u32 a00 = stu[(r) * PAD_A + 8 * kt + c];
            u32 a01 = stu[(r + 8) * PAD_A + 8 * kt + c];
            u32 a02 = stu[(r) * PAD_A + 8 * kt + c + 4];
            u32 a03 = stu[(r + 8) * PAD_A + 8 * kt + c + 4];
            u32 a10 = stu[(r + 16) * PAD_A + 8 * kt + c];
            u32 a11 = stu[(r + 24) * PAD_A + 8 * kt + c];
            u32 a12 = stu[(r + 16) * PAD_A + 8 * kt + c + 4];
            u32 a13 = stu[(r + 24) * PAD_A + 8 * kt + c + 4];
#pragma unroll
            for (int nt = 0; nt < 8; nt++) {
                u32 b0 = smu[OFF_W1 + (8 * kt + c) * PAD_W1 + 8 * nt + r];
                u32 b1 = smu[OFF_W1 + (8 * kt + c + 4) * PAD_W1 + 8 * nt + r];
                mma8(d1 + nt * 4, a00, a01, a02, a03, b0, b1);
                mma8(d1 + 32 + nt * 4, a10, a11, a12, a13, b0, b1);
            }
        }
        __syncwarp();

        // ===== H1 = leaky(D1 + b1), restage as tf32 (FC2 A operand) =====
#pragma unroll
        for (int nt = 0; nt < 8; nt++) {
            float blo = smf[OFF_B1 + 8 * nt + 2 * c];
            float bhi = smf[OFF_B1 + 8 * nt + 2 * c + 1];
#pragma unroll
            for (int mt = 0; mt < 2; mt++) {
                float *dd = d1 + mt * 32 + nt * 4;
                int rb = mt * 16;
                stu[(rb + r) * PAD_A + 8 * nt + 2 * c] = tf32(leaky(dd[0] + blo));
                stu[(rb + r) * PAD_A + 8 * nt + 2 * c + 1] = tf32(leaky(dd[1] + bhi));
                stu[(rb + r + 8) * PAD_A + 8 * nt + 2 * c] = tf32(leaky(dd[2] + blo));
                stu[(rb + r + 8) * PAD_A + 8 * nt + 2 * c + 1] = tf32(leaky(dd[3] + bhi));
            }
        }
        __syncwarp();

        // ===== FC2: D[32x16] = H1[32x64] @ W2[64x16] =====
        float d2[16];
#pragma unroll
        for (int q = 0; q < 16; q++) d2[q] = 0.0f;
#pragma unroll
        for (int kt = 0; kt < 8; kt++) {
            u32 a00 = stu[(r) * PAD_A + 8 * kt + c];
            u32 a01 = stu[(r + 8) * PAD_A + 8 * kt + c];
            u32 a02 = stu[(r) * PAD_A + 8 * kt + c + 4];
            u32 a03 = stu[(r + 8) * PAD_A + 8 * kt + c + 4];
            u32 a10 = stu[(r + 16) * PAD_A + 8 * kt + c];
            u32 a11 = stu[(r + 24) * PAD_A + 8 * kt + c];
            u32 a12 = stu[(r + 16) * PAD_A + 8 * kt + c + 4];
            u32 a13 = stu[(r + 24) * PAD_A + 8 * kt + c + 4];
#pragma unroll
            for (int nt = 0; nt < 2; nt++) {
                u32 b0 = smu[OFF_W2 + (8 * kt + c) * PAD_W2 + 8 * nt + r];
                u32 b1 = smu[OFF_W2 + (8 * kt + c + 4) * PAD_W2 + 8 * nt + r];
                mma8(d2 + nt * 4, a00, a01, a02, a03, b0, b1);
                mma8(d2 + 8 + nt * 4, a10, a11, a12, a13, b0, b1);
            }
        }
        __syncwarp();

        // ===== H2 = leaky(D2 + b2) -> restage fp32 for per-point head =====
#pragma unroll
        for (int nt = 0; nt < 2; nt++) {
            float blo = smf[OFF_B2 + 8 * nt + 2 * c];
            float bhi = smf[OFF_B2 + 8 * nt + 2 * c + 1];
#pragma unroll
            for (int mt = 0; mt < 2; mt++) {
                float *dd = d2 + mt * 8 + nt * 4;
                int rb = mt * 16;
                stf[(rb + r) * PAD_A + 8 * nt + 2 * c] = leaky(dd[0] + blo);
                stf[(rb + r) * PAD_A + 8 * nt + 2 * c + 1] = leaky(dd[1] + bhi);
                stf[(rb + r + 8) * PAD_A + 8 * nt + 2 * c] = leaky(dd[2] + blo);
                stf[(rb + r + 8) * PAD_A + 8 * nt + 2 * c + 1] = leaky(dd[3] + bhi);
            }
        }
        __syncwarp();

        // ===== head: FC3 (16->8, smem broadcast weights) + FC4 + sigmoid*255 =====
        float a2[16];
#pragma unroll
        for (int q = 0; q < 4; q++) {
            float4 v = *(const float4 *)&stf[lane * PAD_A + 4 * q];
            a2[4 * q + 0] = v.x;
            a2[4 * q + 1] = v.y;
            a2[4 * q + 2] = v.z;
            a2[4 * q + 3] = v.w;
        }
        u64 h3[4];
#pragma unroll
        for (int q = 0; q < 4; q++) h3[q] = pack2(cB3[2 * q], cB3[2 * q + 1]);
#pragma unroll
        for (int j = 0; j < 16; j++) {
            float a = a2[j];
            u64 av = pack2(a, a);
            const ulonglong2 *w = (const ulonglong2 *)&smf[OFF_W3 + j * 8];
            ulonglong2 w01 = w[0], w23 = w[1];
            fma2(h3[0], av, w01.x);
            fma2(h3[1], av, w01.y);
            fma2(h3[2], av, w23.x);
            fma2(h3[3], av, w23.y);
        }
        float o0 = cB4[0], o1 = cB4[1], o2 = cB4[2];
#pragma unroll
        for (int q = 0; q < 4; q++) {
            float2 v = unpack2(h3[q]);
            float a0 = leaky(v.x), a1 = leaky(v.y);
            int i0 = 2 * q, i1 = 2 * q + 1;
            o0 = fmaf(a0, cW4[i0 * 3 + 0], o0);
            o1 = fmaf(a0, cW4[i0 * 3 + 1], o1);
            o2 = fmaf(a0, cW4[i0 * 3 + 2], o2);
            o0 = fmaf(a1, cW4[i1 * 3 + 0], o0);
            o1 = fmaf(a1, cW4[i1 * 3 + 1], o1);
            o2 = fmaf(a1, cW4[i1 * 3 + 2], o2);
        }
        o0 = sigmoidf(leaky(o0)) * 255.0f;
        o1 = sigmoidf(leaky(o1)) * 255.0f;
        o2 = sigmoidf(leaky(o2)) * 255.0f;

        if (p < n) {
            out[p * 3 + 0] = o0;
            out[p * 3 + 1] = o1;
            out[p * 3 + 2] = o2;
        }
        __syncwarp();  // stage reuse across tile iterations
    }
}

extern "C" void kernel_launch(void *const *d_in, const int *in_sizes, int n_in,
                              void *d_out, int out_size)
{
    const float *pos = (const float *)d_in[0];
    const float *dir = (const float *)d_in[1];
    const float *pos_grid = (const float *)d_in[2];
    const float *dir_grid = (const float *)d_in[3];

    cudaMemcpyToSymbolAsync(cEnc, d_in[4], 8 * sizeof(float), 0, cudaMemcpyDeviceToDevice, 0);
    cudaMemcpyToSymbolAsync(cEnc, d_in[5], 4 * sizeof(float), 8 * sizeof(float), cudaMemcpyDeviceToDevice, 0);
    cudaMemcpyToSymbolAsync(cEnc, d_in[6], 12 * sizeof(float), 12 * sizeof(float), cudaMemcpyDeviceToDevice, 0);
    cudaMemcpyToSymbolAsync(cEnc, d_in[7], 3 * sizeof(float), 24 * sizeof(float), cudaMemcpyDeviceToDevice, 0);
    cudaMemcpyToSymbolAsync(cB3, d_in[13], 8 * sizeof(float), 0, cudaMemcpyDeviceToDevice, 0);
    cudaMemcpyToSymbolAsync(cW4, d_in[14], 8 * 3 * sizeof(float), 0, cudaMemcpyDeviceToDevice, 0);
    cudaMemcpyToSymbolAsync(cB4, d_in[15], 3 * sizeof(float), 0, cudaMemcpyDeviceToDevice, 0);

    cudaFuncSetAttribute(gridnet_hmma, cudaFuncAttributeMaxDynamicSharedMemorySize, DYN_BYTES);

    float *out = (float *)d_out;
    int n = in_sizes[0] / 2;
    int ntiles = (n + 127) / 128;
    int blocks = 148 * 3;
    if (blocks > ntiles) blocks = ntiles;
    gridnet_hmma<<<blocks, 128, DYN_BYTES>>>(
        pos, dir, pos_grid, dir_grid,
        (const float *)d_in[8], (const float *)d_in[9],
        (const float *)d_in[10], (const float *)d_in[11],
        (const float *)d_in[12],
        out, n, ntiles);
}

// round 9
// speedup vs baseline: 3.8849x; 1.3930x over previous
#include <cuda_runtime.h>
#include <stdint.h>

typedef unsigned long long u64;
typedef unsigned int u32;

// ---------------- cmem: small uniform-read constants ----------------
__constant__ __align__(16) float cW3[16 * 8];
__constant__ __align__(16) float cW4[8 * 3];
__constant__ __align__(16) float cB3[8];
__constant__ __align__(16) float cB4[3];
__constant__ __align__(16) float cEnc[27];

// ---------------- dyn smem layout (u32 word offsets) ----------------
#define OFF_W1T 0        // [n=64][36] bf16x2 words (k2 0..31 used)
#define OFF_W2T 2304     // [n=16][36]
#define OFF_B1 2880      // 64 f32
#define OFF_B2 2944      // 16 f32
#define META_U64_OFF 1480  // u64 index (byte 11840); [warp][idx=8][33] u64
#define OFF_SX 5072      // feature / H2 stage: 4 warps x 32 rows x 32 words
#define OFF_SH 9168      // H1 stage: same shape
#define DYN_BYTES 53248

// ---------------- helpers ----------------
static __device__ __forceinline__ u64 pack2(float lo, float hi) {
    u64 r; asm("mov.b64 %0, {%1, %2};" : "=l"(r) : "f"(lo), "f"(hi)); return r;
}
static __device__ __forceinline__ float2 unpack2(u64 v) {
    float2 f; asm("mov.b64 {%0, %1}, %2;" : "=f"(f.x), "=f"(f.y) : "l"(v)); return f;
}
static __device__ __forceinline__ void fma2(u64 &d, u64 a, u64 b) {
    asm("fma.rn.f32x2 %0, %1, %2, %0;" : "+l"(d) : "l"(a), "l"(b));
}
// pack two f32 into bf16x2: lo -> bits[15:0], hi -> bits[31:16]
static __device__ __forceinline__ u32 pack_bf16(float lo, float hi) {
    u32 d; asm("cvt.rn.bf16x2.f32 %0, %1, %2;" : "=r"(d) : "f"(hi), "f"(lo)); return d;
}
static __device__ __forceinline__ void mma_bf16(float *d, u32 a0, u32 a1, u32 a2, u32 a3,
                                                u32 b0, u32 b1) {
    asm("mma.sync.aligned.m16n8k16.row.col.f32.bf16.bf16.f32 "
        "{%0,%1,%2,%3},{%4,%5,%6,%7},{%8,%9},{%0,%1,%2,%3};"
        : "+f"(d[0]), "+f"(d[1]), "+f"(d[2]), "+f"(d[3])
        : "r"(a0), "r"(a1), "r"(a2), "r"(a3), "r"(b0), "r"(b1));
}
static __device__ __forceinline__ float leaky(float x) { return fmaxf(x, 0.01f * x); }
static __device__ __forceinline__ float sigmoidf(float x) { return 1.0f / (1.0f + __expf(-x)); }
static __device__ __forceinline__ float tanh_fast(float x) {
    return fmaf(2.0f, sigmoidf(2.0f * x), -1.0f);
}
static __device__ __forceinline__ void encode(float i0, float i1, float &x, float &y) {
    float h[4];
#pragma unroll
    for (int j = 0; j < 4; j++)
        h[j] = tanh_fast(fmaf(i0, cEnc[j], fmaf(i1, cEnc[4 + j], cEnc[8 + j])));
    float z0 = cEnc[24], z1 = cEnc[25];
#pragma unroll
    for (int j = 0; j < 4; j++) {
        z0 = fmaf(h[j], cEnc[12 + j * 3 + 0], z0);
        z1 = fmaf(h[j], cEnc[12 + j * 3 + 1], z1);
    }
    x = sigmoidf(z0) * 255.0f;
    y = sigmoidf(z1) * 255.0f;
}

// ---------------- kernel ----------------
__global__ void __launch_bounds__(128, 4) gridnet_bf16(
    const float *__restrict__ pos, const float *__restrict__ dir,
    const float *__restrict__ pos_grid, const float *__restrict__ dir_grid,
    const float *__restrict__ fc_w1, const float *__restrict__ fc_b1,
    const float *__restrict__ fc_w2, const float *__restrict__ fc_b2,
    float *__restrict__ out, int n, int ntiles)
{
    extern __shared__ __align__(16) char smraw[];
    u32 *sm = (u32 *)smraw;
    float *smf = (float *)smraw;

    const int tid = threadIdx.x;
    const int warp = tid >> 5, lane = tid & 31;
    const int grp = lane >> 3, f = lane & 7;   // loader roles
    const int r = lane >> 2, c = lane & 3;     // mma fragment roles

    // ---- stage weights once per CTA (bf16x2 transposed [n][k2])
    for (int i = tid; i < 64 * 36; i += 128) {
        int nn = i / 36, k2 = i % 36;
        u32 v = 0;
        if (k2 < 32) v = pack_bf16(fc_w1[(2 * k2) * 64 + nn], fc_w1[(2 * k2 + 1) * 64 + nn]);
        sm[OFF_W1T + i] = v;
    }
    for (int i = tid; i < 16 * 36; i += 128) {
        int nn = i / 36, k2 = i % 36;
        u32 v = 0;
        if (k2 < 32) v = pack_bf16(fc_w2[(2 * k2) * 16 + nn], fc_w2[(2 * k2 + 1) * 16 + nn]);
        sm[OFF_W2T + i] = v;
    }
    if (tid < 64) smf[OFF_B1 + tid] = fc_b1[tid];
    if (tid < 16) smf[OFF_B2 + tid] = fc_b2[tid];
    __syncthreads();

    u32 *sx = sm + OFF_SX + warp * 1024;
    u32 *sh = sm + OFF_SH + warp * 1024;
    float *sxf = (float *)sx;
    u64 *mw = (u64 *)smraw + META_U64_OFF + warp * 264;  // [idx=8][33]

    const int rb0 = r * 32, rb1 = (r + 8) * 32, rb2 = (r + 16) * 32, rb3 = (r + 24) * 32;

    for (int tile = blockIdx.x; tile < ntiles; tile += gridDim.x) {
        const int p = tile * 128 + warp * 32 + lane;
        const int pc = min(p, n - 1);

        // ===== owner: encode -> corner metadata (transposed meta: [idx][row]) =====
        {
            float gx[2], gy[2];
            float a0 = pos[2 * pc], a1 = pos[2 * pc + 1];
            float e0 = dir[2 * pc], e1 = dir[2 * pc + 1];
            encode(a0, a1, gx[0], gy[0]);
            encode(e0, e1, gx[1], gy[1]);
#pragma unroll
            for (int g = 0; g < 2; g++) {
                float x = gx[g], y = gy[g];
                int x0 = min((int)x, 255), y0 = min((int)y, 255);
                float xf = x - (float)x0, yf = y - (float)y0;
                int x1 = min(x0 + 1, 255), y1 = min(y0 + 1, 255);
                u32 o0 = (u32)(y0 * 256 + x0) * 128u;
                u32 o1 = (u32)(y0 * 256 + x1) * 128u;
                u32 o2 = (u32)(y1 * 256 + x0) * 128u;
                u32 o3 = (u32)(y1 * 256 + x1) * 128u;
                float w0 = (1.0f - xf) * (1.0f - yf);
                float w1 = xf * (1.0f - yf);
                float w2 = (1.0f - xf) * yf;
                float w3 = xf * yf;
                mw[(g * 4 + 0) * 33 + lane] = (u64)o0 | ((u64)__float_as_uint(w0) << 32);
                mw[(g * 4 + 1) * 33 + lane] = (u64)o1 | ((u64)__float_as_uint(w1) << 32);
                mw[(g * 4 + 2) * 33 + lane] = (u64)o2 | ((u64)__float_as_uint(w2) << 32);
                mw[(g * 4 + 3) * 33 + lane] = (u64)o3 | ((u64)__float_as_uint(w3) << 32);
            }
        }
        __syncwarp();

        // ===== loader: coop gather + blend -> bf16x2 rotated stage =====
#pragma unroll 1
        for (int g = 0; g < 2; g++) {
            const float *gbase = (g == 0) ? pos_grid : dir_grid;
#pragma unroll
            for (int i = 0; i < 8; i++) {
                int row = i * 4 + grp;
                u64 acc01 = 0, acc23 = 0;
#pragma unroll
                for (int cc = 0; cc < 4; cc++) {
                    u64 mwv = mw[(g * 4 + cc) * 33 + row];
                    u32 off = (u32)mwv;
                    float w = __uint_as_float((u32)(mwv >> 32));
                    float4 v = __ldg((const float4 *)((const char *)gbase + off) + f);
                    u64 wv = pack2(w, w);
                    fma2(acc01, wv, pack2(v.x, v.y));
                    fma2(acc23, wv, pack2(v.z, v.w));
                }
                float2 lo = unpack2(acc01), hi = unpack2(acc23);
                u32 w0 = pack_bf16(lo.x, lo.y);
                u32 w1 = pack_bf16(hi.x, hi.y);
                int k2 = g * 16 + 2 * f;
                int word = row * 32 + ((k2 + 4 * row) & 31);
                *(u64 *)&sx[word] = (u64)w0 | ((u64)w1 << 32);
            }
        }
        __syncwarp();

        // ===== FC1: two nt-halves, d1[32] each; restage leaky(+b1) as bf16 -> sh =====
#pragma unroll 1
        for (int half = 0; half < 2; half++) {
            float d1[32];
#pragma unroll
            for (int q = 0; q < 32; q++) d1[q] = 0.0f;
#pragma unroll
            for (int kt = 0; kt < 4; kt++) {
                int rot0 = (8 * kt + c + 4 * r) & 31;
                int rot1 = (rot0 + 4) & 31;
                u32 a00 = sx[rb0 + rot0], a01 = sx[rb1 + rot0];
                u32 a02 = sx[rb0 + rot1], a03 = sx[rb1 + rot1];
                u32 a10 = sx[rb2 + rot0], a11 = sx[rb3 + rot0];
                u32 a12 = sx[rb2 + rot1], a13 = sx[rb3 + rot1];
#pragma unroll
                for (int ntp = 0; ntp < 4; ntp++) {
                    int nt = half * 4 + ntp;
                    u32 b0 = sm[OFF_W1T + (8 * nt + r) * 36 + 8 * kt + c];
                    u32 b1 = sm[OFF_W1T + (8 * nt + r) * 36 + 8 * kt + c + 4];
                    mma_bf16(d1 + ntp * 8, a00, a01, a02, a03, b0, b1);
                    mma_bf16(d1 + ntp * 8 + 4, a10, a11, a12, a13, b0, b1);
                }
            }
            // restage this half: cols 8nt+2c,+1 -> word k2 = 4nt + c
#pragma unroll
            for (int ntp = 0; ntp < 4; ntp++) {
                int nt = half * 4 + ntp;
                float blo = smf[OFF_B1 + 8 * nt + 2 * c];
                float bhi = smf[OFF_B1 + 8 * nt + 2 * c + 1];
                const float *dd = d1 + ntp * 8;
                int rot = (4 * nt + c + 4 * r) & 31;
                sh[rb0 + rot] = pack_bf16(leaky(dd[0] + blo), leaky(dd[1] + bhi));
                sh[rb1 + rot] = pack_bf16(leaky(dd[2] + blo), leaky(dd[3] + bhi));
                sh[rb2 + rot] = pack_bf16(leaky(dd[4] + blo), leaky(dd[5] + bhi));
                sh[rb3 + rot] = pack_bf16(leaky(dd[6] + blo), leaky(dd[7] + bhi));
            }
        }
        __syncwarp();

        // ===== FC2: d2[16] = H1[32x64] @ W2[64x16] =====
        float d2[16];
#pragma unroll
        for (int q = 0; q < 16; q++) d2[q] = 0.0f;
#pragma unroll
        for (int kt = 0; kt < 4; kt++) {
            int rot0 = (8 * kt + c + 4 * r) & 31;
            int rot1 = (rot0 + 4) & 31;
            u32 a00 = sh[rb0 + rot0], a01 = sh[rb1 + rot0];
            u32 a02 = sh[rb0 + rot1], a03 = sh[rb1 + rot1];
            u32 a10 = sh[rb2 + rot0], a11 = sh[rb3 + rot0];
            u32 a12 = sh[rb2 + rot1], a13 = sh[rb3 + rot1];
#pragma unroll
            for (int nt = 0; nt < 2; nt++) {
                u32 b0 = sm[OFF_W2T + (8 * nt + r) * 36 + 8 * kt + c];
                u32 b1 = sm[OFF_W2T + (8 * nt + r) * 36 + 8 * kt + c + 4];
                mma_bf16(d2 + nt * 8, a00, a01, a02, a03, b0, b1);
                mma_bf16(d2 + nt * 8 + 4, a10, a11, a12, a13, b0, b1);
            }
        }

        // ===== H2 = leaky(D2 + b2) -> f32 restage into sx (rotated cols 0..15) =====
#pragma unroll
        for (int nt = 0; nt < 2; nt++) {
            float blo = smf[OFF_B2 + 8 * nt + 2 * c];
            float bhi = smf[OFF_B2 + 8 * nt + 2 * c + 1];
            const float *dd = d2 + nt * 8;
            int rot = (8 * nt + 2 * c + 4 * r) & 31;
            *(u64 *)&sxf[rb0 + rot] = pack2(leaky(dd[0] + blo), leaky(dd[1] + bhi));
            *(u64 *)&sxf[rb1 + rot] = pack2(leaky(dd[2] + blo), leaky(dd[3] + bhi));
            *(u64 *)&sxf[rb2 + rot] = pack2(leaky(dd[4] + blo), leaky(dd[5] + bhi));
            *(u64 *)&sxf[rb3 + rot] = pack2(leaky(dd[6] + blo), leaky(dd[7] + bhi));
        }
        __syncwarp();

        // ===== head: FC3 (16->8, cmem uniform) + FC4 + sigmoid*255 =====
        float a2[16];
#pragma unroll
        for (int q = 0; q < 4; q++) {
            float4 v = *(const float4 *)&sxf[lane * 32 + ((4 * q + 4 * lane) & 31)];
            a2[4 * q + 0] = v.x;
            a2[4 * q + 1] = v.y;
            a2[4 * q + 2] = v.z;
            a2[4 * q + 3] = v.w;
        }
        u64 h3[4];
#pragma unroll
        for (int q = 0; q < 4; q++) h3[q] = pack2(cB3[2 * q], cB3[2 * q + 1]);
#pragma unroll
        for (int j = 0; j < 16; j++) {
            float a = a2[j];
            u64 av = pack2(a, a);
            const ulonglong2 *w = (const ulonglong2 *)(cW3 + j * 8);
            ulonglong2 w01 = w[0], w23 = w[1];
            fma2(h3[0], av, w01.x);
            fma2(h3[1], av, w01.y);
            fma2(h3[2], av, w23.x);
            fma2(h3[3], av, w23.y);
        }
        float o0 = cB4[0], o1 = cB4[1], o2 = cB4[2];
#pragma unroll
        for (int q = 0; q < 4; q++) {
            float2 v = unpack2(h3[q]);
            float a0 = leaky(v.x), a1 = leaky(v.y);
            int i0 = 2 * q, i1 = 2 * q + 1;
            o0 = fmaf(a0, cW4[i0 * 3 + 0], o0);
            o1 = fmaf(a0, cW4[i0 * 3 + 1], o1);
            o2 = fmaf(a0, cW4[i0 * 3 + 2], o2);
            o0 = fmaf(a1, cW4[i1 * 3 + 0], o0);
            o1 = fmaf(a1, cW4[i1 * 3 + 1], o1);
            o2 = fmaf(a1, cW4[i1 * 3 + 2], o2);
        }
        o0 = sigmoidf(leaky(o0)) * 255.0f;
        o1 = sigmoidf(leaky(o1)) * 255.0f;
        o2 = sigmoidf(leaky(o2)) * 255.0f;

        if (p < n) {
            out[p * 3 + 0] = o0;
            out[p * 3 + 1] = o1;
            out[p * 3 + 2] = o2;
        }
        __syncwarp();  // stage/meta reuse across tiles
    }
}

extern "C" void kernel_launch(void *const *d_in, const int *in_sizes, int n_in,
                              void *d_out, int out_size)
{
    const float *pos = (const float *)d_in[0];
    const float *dir = (const float *)d_in[1];
    const float *pos_grid = (const float *)d_in[2];
    const float *dir_grid = (const float *)d_in[3];

    cudaMemcpyToSymbolAsync(cEnc, d_in[4], 8 * sizeof(float), 0, cudaMemcpyDeviceToDevice, 0);
    cudaMemcpyToSymbolAsync(cEnc, d_in[5], 4 * sizeof(float), 8 * sizeof(float), cudaMemcpyDeviceToDevice, 0);
    cudaMemcpyToSymbolAsync(cEnc, d_in[6], 12 * sizeof(float), 12 * sizeof(float), cudaMemcpyDeviceToDevice, 0);
    cudaMemcpyToSymbolAsync(cEnc, d_in[7], 3 * sizeof(float), 24 * sizeof(float), cudaMemcpyDeviceToDevice, 0);
    cudaMemcpyToSymbolAsync(cW3, d_in[12], 16 * 8 * sizeof(float), 0, cudaMemcpyDeviceToDevice, 0);
    cudaMemcpyToSymbolAsync(cB3, d_in[13], 8 * sizeof(float), 0, cudaMemcpyDeviceToDevice, 0);
    cudaMemcpyToSymbolAsync(cW4, d_in[14], 8 * 3 * sizeof(float), 0, cudaMemcpyDeviceToDevice, 0);
    cudaMemcpyToSymbolAsync(cB4, d_in[15], 3 * sizeof(float), 0, cudaMemcpyDeviceToDevice, 0);

    cudaFuncSetAttribute(gridnet_bf16, cudaFuncAttributeMaxDynamicSharedMemorySize, DYN_BYTES);

    float *out = (float *)d_out;
    int n = in_sizes[0] / 2;
    int ntiles = (n + 127) / 128;
    int blocks = 148 * 4;
    if (blocks > ntiles) blocks = ntiles;
    gridnet_bf16<<<blocks, 128, DYN_BYTES>>>(
        pos, dir, pos_grid, dir_grid,
        (const float *)d_in[8], (const float *)d_in[9],
        (const float *)d_in[10], (const float *)d_in[11],
        out, n, ntiles);
}

// round 10
// speedup vs baseline: 3.9924x; 1.0277x over previous
#include <cuda_runtime.h>
#include <stdint.h>

typedef unsigned long long u64;
typedef unsigned int u32;

// ---------------- cmem: small uniform-read constants ----------------
__constant__ __align__(16) float cW3[16 * 8];
__constant__ __align__(16) float cW4[8 * 3];
__constant__ __align__(16) float cB3[8];
__constant__ __align__(16) float cB4[3];
__constant__ __align__(16) float cEnc[27];

// bf16-converted grids: [2][256*256*16 u32 words] (each word = 2 features)
__device__ __align__(16) u32 g_bf16[2 * 1048576];

// ---------------- dyn smem layout (u32 word offsets) ----------------
#define OFF_W1T 0          // [n=64][36] bf16x2 words (k2 0..31 used)
#define OFF_W2T 2304       // [n=16][36]
#define OFF_B1 2880        // 64 f32
#define OFF_B2 2944        // 16 f32
#define META_U64_OFF 1480  // u64 index (byte 11840); [warp][idx=8][33] u64
#define OFF_SX 5072        // feature / H2 stage: 4 warps x 32 rows x 32 words
#define DYN_BYTES 36864

// ---------------- helpers ----------------
static __device__ __forceinline__ u64 pack2(float lo, float hi) {
    u64 r; asm("mov.b64 %0, {%1, %2};" : "=l"(r) : "f"(lo), "f"(hi)); return r;
}
static __device__ __forceinline__ float2 unpack2(u64 v) {
    float2 f; asm("mov.b64 {%0, %1}, %2;" : "=f"(f.x), "=f"(f.y) : "l"(v)); return f;
}
static __device__ __forceinline__ void fma2(u64 &d, u64 a, u64 b) {
    asm("fma.rn.f32x2 %0, %1, %2, %0;" : "+l"(d) : "l"(a), "l"(b));
}
// pack two f32 into bf16x2: lo -> bits[15:0], hi -> bits[31:16]
static __device__ __forceinline__ u32 pack_bf16(float lo, float hi) {
    u32 d; asm("cvt.rn.bf16x2.f32 %0, %1, %2;" : "=r"(d) : "f"(hi), "f"(lo)); return d;
}
static __device__ __forceinline__ void mma_bf16(float *d, u32 a0, u32 a1, u32 a2, u32 a3,
                                                u32 b0, u32 b1) {
    asm("mma.sync.aligned.m16n8k16.row.col.f32.bf16.bf16.f32 "
        "{%0,%1,%2,%3},{%4,%5,%6,%7},{%8,%9},{%0,%1,%2,%3};"
        : "+f"(d[0]), "+f"(d[1]), "+f"(d[2]), "+f"(d[3])
        : "r"(a0), "r"(a1), "r"(a2), "r"(a3), "r"(b0), "r"(b1));
}
static __device__ __forceinline__ float leaky(float x) { return fmaxf(x, 0.01f * x); }
static __device__ __forceinline__ float sigmoidf(float x) { return 1.0f / (1.0f + __expf(-x)); }
static __device__ __forceinline__ float tanh_fast(float x) {
    return fmaf(2.0f, sigmoidf(2.0f * x), -1.0f);
}
static __device__ __forceinline__ void encode(float i0, float i1, float &x, float &y) {
    float h[4];
#pragma unroll
    for (int j = 0; j < 4; j++)
        h[j] = tanh_fast(fmaf(i0, cEnc[j], fmaf(i1, cEnc[4 + j], cEnc[8 + j])));
    float z0 = cEnc[24], z1 = cEnc[25];
#pragma unroll
    for (int j = 0; j < 4; j++) {
        z0 = fmaf(h[j], cEnc[12 + j * 3 + 0], z0);
        z1 = fmaf(h[j], cEnc[12 + j * 3 + 1], z1);
    }
    x = sigmoidf(z0) * 255.0f;
    y = sigmoidf(z1) * 255.0f;
}

// ---------------- grid pre-conversion: fp32 -> bf16x2 ----------------
__global__ void __launch_bounds__(256) convert_grids(
    const float *__restrict__ g0, const float *__restrict__ g1)
{
    int i = blockIdx.x * 256 + threadIdx.x;  // one float4 -> one u64
    const float *src = (i < 524288) ? g0 : g1;
    int j = i & 524287;
    float4 v = __ldg((const float4 *)src + j);
    u64 w = (u64)pack_bf16(v.x, v.y) | ((u64)pack_bf16(v.z, v.w) << 32);
    *((u64 *)g_bf16 + i) = w;
}

// ---------------- main kernel ----------------
__global__ void __launch_bounds__(128, 4) gridnet_fused16(
    const float *__restrict__ pos, const float *__restrict__ dir,
    const float *__restrict__ fc_w1, const float *__restrict__ fc_b1,
    const float *__restrict__ fc_w2, const float *__restrict__ fc_b2,
    float *__restrict__ out, int n, int ntiles)
{
    extern __shared__ __align__(16) char smraw[];
    u32 *sm = (u32 *)smraw;
    float *smf = (float *)smraw;

    const int tid = threadIdx.x;
    const int warp = tid >> 5, lane = tid & 31;
    const int grp = lane >> 3, f = lane & 7;   // loader roles
    const int r = lane >> 2, c = lane & 3;     // mma fragment roles

    // ---- stage weights once per CTA (bf16x2 transposed [n][k2])
    for (int i = tid; i < 64 * 36; i += 128) {
        int nn = i / 36, k2 = i % 36;
        u32 v = 0;
        if (k2 < 32) v = pack_bf16(fc_w1[(2 * k2) * 64 + nn], fc_w1[(2 * k2 + 1) * 64 + nn]);
        sm[OFF_W1T + i] = v;
    }
    for (int i = tid; i < 16 * 36; i += 128) {
        int nn = i / 36, k2 = i % 36;
        u32 v = 0;
        if (k2 < 32) v = pack_bf16(fc_w2[(2 * k2) * 16 + nn], fc_w2[(2 * k2 + 1) * 16 + nn]);
        sm[OFF_W2T + i] = v;
    }
    if (tid < 64) smf[OFF_B1 + tid] = fc_b1[tid];
    if (tid < 16) smf[OFF_B2 + tid] = fc_b2[tid];
    __syncthreads();

    u32 *sx = sm + OFF_SX + warp * 1024;
    float *sxf = (float *)sx;
    u64 *mw = (u64 *)smraw + META_U64_OFF + warp * 264;  // [idx=8][33]

    const int rb0 = r * 32, rb1 = (r + 8) * 32, rb2 = (r + 16) * 32, rb3 = (r + 24) * 32;

    for (int tile = blockIdx.x; tile < ntiles; tile += gridDim.x) {
        const int p = tile * 128 + warp * 32 + lane;
        const int pc = min(p, n - 1);

        // ===== owner: encode -> corner metadata (offsets into bf16 grid: 64B rows) =====
        {
            float gx[2], gy[2];
            float a0 = pos[2 * pc], a1 = pos[2 * pc + 1];
            float e0 = dir[2 * pc], e1 = dir[2 * pc + 1];
            encode(a0, a1, gx[0], gy[0]);
            encode(e0, e1, gx[1], gy[1]);
#pragma unroll
            for (int g = 0; g < 2; g++) {
                float x = gx[g], y = gy[g];
                int x0 = min((int)x, 255), y0 = min((int)y, 255);
                float xf = x - (float)x0, yf = y - (float)y0;
                int x1 = min(x0 + 1, 255), y1 = min(y0 + 1, 255);
                u32 o0 = (u32)(y0 * 256 + x0) * 64u;
                u32 o1 = (u32)(y0 * 256 + x1) * 64u;
                u32 o2 = (u32)(y1 * 256 + x0) * 64u;
                u32 o3 = (u32)(y1 * 256 + x1) * 64u;
                float w0 = (1.0f - xf) * (1.0f - yf);
                float w1 = xf * (1.0f - yf);
                float w2 = (1.0f - xf) * yf;
                float w3 = xf * yf;
                mw[(g * 4 + 0) * 33 + lane] = (u64)o0 | ((u64)__float_as_uint(w0) << 32);
                mw[(g * 4 + 1) * 33 + lane] = (u64)o1 | ((u64)__float_as_uint(w1) << 32);
                mw[(g * 4 + 2) * 33 + lane] = (u64)o2 | ((u64)__float_as_uint(w2) << 32);
                mw[(g * 4 + 3) * 33 + lane] = (u64)o3 | ((u64)__float_as_uint(w3) << 32);
            }
        }
        __syncwarp();

        // ===== loader: coop gather (bf16 rows) + f32 blend -> bf16x2 rotated stage =====
#pragma unroll 1
        for (int g = 0; g < 2; g++) {
            const char *gbase = (const char *)(g_bf16 + (u32)g * 1048576u);
#pragma unroll
            for (int i = 0; i < 8; i++) {
                int row = i * 4 + grp;
                u64 acc01 = 0, acc23 = 0;
#pragma unroll
                for (int cc = 0; cc < 4; cc++) {
                    u64 mwv = mw[(g * 4 + cc) * 33 + row];
                    u32 off = (u32)mwv;
                    float w = __uint_as_float((u32)(mwv >> 32));
                    u64 vw = __ldg((const u64 *)(gbase + off) + f);
                    u32 wlo = (u32)vw, whi = (u32)(vw >> 32);
                    float f0 = __uint_as_float(wlo << 16);
                    float f1 = __uint_as_float(wlo & 0xFFFF0000u);
                    float f2 = __uint_as_float(whi << 16);
                    float f3 = __uint_as_float(whi & 0xFFFF0000u);
                    u64 wv = pack2(w, w);
                    fma2(acc01, wv, pack2(f0, f1));
                    fma2(acc23, wv, pack2(f2, f3));
                }
                float2 lo = unpack2(acc01), hi = unpack2(acc23);
                u32 w0 = pack_bf16(lo.x, lo.y);
                u32 w1 = pack_bf16(hi.x, hi.y);
                int k2 = g * 16 + 2 * f;
                int word = row * 32 + ((k2 + 4 * row) & 31);
                *(u64 *)&sx[word] = (u64)w0 | ((u64)w1 << 32);
            }
        }
        __syncwarp();

        // ===== FC1 + FC2 fused: per half, D1-frags feed FC2 A-frags in registers =====
        float d2[16];
#pragma unroll
        for (int q = 0; q < 16; q++) d2[q] = 0.0f;

#pragma unroll 1
        for (int half = 0; half < 2; half++) {
            float d1[32];
#pragma unroll
            for (int q = 0; q < 32; q++) d1[q] = 0.0f;
#pragma unroll
            for (int kt = 0; kt < 4; kt++) {
                int rot0 = (8 * kt + c + 4 * r) & 31;
                int rot1 = (rot0 + 4) & 31;
                u32 a00 = sx[rb0 + rot0], a01 = sx[rb1 + rot0];
                u32 a02 = sx[rb0 + rot1], a03 = sx[rb1 + rot1];
                u32 a10 = sx[rb2 + rot0], a11 = sx[rb3 + rot0];
                u32 a12 = sx[rb2 + rot1], a13 = sx[rb3 + rot1];
#pragma unroll
                for (int ntp = 0; ntp < 4; ntp++) {
                    int nt = half * 4 + ntp;
                    u32 b0 = sm[OFF_W1T + (8 * nt + r) * 36 + 8 * kt + c];
                    u32 b1 = sm[OFF_W1T + (8 * nt + r) * 36 + 8 * kt + c + 4];
                    mma_bf16(d1 + ntp * 8, a00, a01, a02, a03, b0, b1);
                    mma_bf16(d1 + ntp * 8 + 4, a10, a11, a12, a13, b0, b1);
                }
            }
            // FC2 partial: k-tiles kt2 = 2*half + ktp; A-frags straight from d1 regs
#pragma unroll
            for (int ktp = 0; ktp < 2; ktp++) {
                const float *dA0 = d1 + (2 * ktp) * 8;      // nt = half*4 + 2*ktp
                const float *dA1 = d1 + (2 * ktp + 1) * 8;  // nt+1
                int ntA0 = half * 4 + 2 * ktp, ntA1 = ntA0 + 1;
                float blo0 = smf[OFF_B1 + 8 * ntA0 + 2 * c];
                float bhi0 = smf[OFF_B1 + 8 * ntA0 + 2 * c + 1];
                float blo1 = smf[OFF_B1 + 8 * ntA1 + 2 * c];
                float bhi1 = smf[OFF_B1 + 8 * ntA1 + 2 * c + 1];
                u32 a0 = pack_bf16(leaky(dA0[0] + blo0), leaky(dA0[1] + bhi0));
                u32 a1 = pack_bf16(leaky(dA0[2] + blo0), leaky(dA0[3] + bhi0));
                u32 a2 = pack_bf16(leaky(dA1[0] + blo1), leaky(dA1[1] + bhi1));
                u32 a3 = pack_bf16(leaky(dA1[2] + blo1), leaky(dA1[3] + bhi1));
                u32 a10 = pack_bf16(leaky(dA0[4] + blo0), leaky(dA0[5] + bhi0));
                u32 a11 = pack_bf16(leaky(dA0[6] + blo0), leaky(dA0[7] + bhi0));
                u32 a12 = pack_bf16(leaky(dA1[4] + blo1), leaky(dA1[5] + bhi1));
                u32 a13 = pack_bf16(leaky(dA1[6] + blo1), leaky(dA1[7] + bhi1));
                int kt2 = half * 2 + ktp;
#pragma unroll
                for (int nt2 = 0; nt2 < 2; nt2++) {
                    u32 b0 = sm[OFF_W2T + (8 * nt2 + r) * 36 + 8 * kt2 + c];
                    u32 b1 = sm[OFF_W2T + (8 * nt2 + r) * 36 + 8 * kt2 + c + 4];
                    mma_bf16(d2 + nt2 * 8, a0, a1, a2, a3, b0, b1);
                    mma_bf16(d2 + nt2 * 8 + 4, a10, a11, a12, a13, b0, b1);
                }
            }
        }
        __syncwarp();

        // ===== H2 = leaky(D2 + b2) -> f32 restage into sx (rotated cols 0..15) =====
#pragma unroll
        for (int nt = 0; nt < 2; nt++) {
            float blo = smf[OFF_B2 + 8 * nt + 2 * c];
            float bhi = smf[OFF_B2 + 8 * nt + 2 * c + 1];
            const float *dd = d2 + nt * 8;
            int rot = (8 * nt + 2 * c + 4 * r) & 31;
            *(u64 *)&sxf[rb0 + rot] = pack2(leaky(dd[0] + blo), leaky(dd[1] + bhi));
            *(u64 *)&sxf[rb1 + rot] = pack2(leaky(dd[2] + blo), leaky(dd[3] + bhi));
            *(u64 *)&sxf[rb2 + rot] = pack2(leaky(dd[4] + blo), leaky(dd[5] + bhi));
            *(u64 *)&sxf[rb3 + rot] = pack2(leaky(dd[6] + blo), leaky(dd[7] + bhi));
        }
        __syncwarp();

        // ===== head: FC3 (16->8, cmem uniform) + FC4 + sigmoid*255 =====
        float a2[16];
#pragma unroll
        for (int q = 0; q < 4; q++) {
            float4 v = *(const float4 *)&sxf[lane * 32 + ((4 * q + 4 * lane) & 31)];
            a2[4 * q + 0] = v.x;
            a2[4 * q + 1] = v.y;
            a2[4 * q + 2] = v.z;
            a2[4 * q + 3] = v.w;
        }
        u64 h3[4];
#pragma unroll
        for (int q = 0; q < 4; q++) h3[q] = pack2(cB3[2 * q], cB3[2 * q + 1]);
#pragma unroll
        for (int j = 0; j < 16; j++) {
            float a = a2[j];
            u64 av = pack2(a, a);
            const ulonglong2 *w = (const ulonglong2 *)(cW3 + j * 8);
            ulonglong2 w01 = w[0], w23 = w[1];
            fma2(h3[0], av, w01.x);
            fma2(h3[1], av, w01.y);
            fma2(h3[2], av, w23.x);
            fma2(h3[3], av, w23.y);
        }
        float o0 = cB4[0], o1 = cB4[1], o2 = cB4[2];
#pragma unroll
        for (int q = 0; q < 4; q++) {
            float2 v = unpack2(h3[q]);
            float a0 = leaky(v.x), a1 = leaky(v.y);
            int i0 = 2 * q, i1 = 2 * q + 1;
            o0 = fmaf(a0, cW4[i0 * 3 + 0], o0);
            o1 = fmaf(a0, cW4[i0 * 3 + 1], o1);
            o2 = fmaf(a0, cW4[i0 * 3 + 2], o2);
            o0 = fmaf(a1, cW4[i1 * 3 + 0], o0);
            o1 = fmaf(a1, cW4[i1 * 3 + 1], o1);
            o2 = fmaf(a1, cW4[i1 * 3 + 2], o2);
        }
        o0 = sigmoidf(leaky(o0)) * 255.0f;
        o1 = sigmoidf(leaky(o1)) * 255.0f;
        o2 = sigmoidf(leaky(o2)) * 255.0f;

        if (p < n) {
            out[p * 3 + 0] = o0;
            out[p * 3 + 1] = o1;
            out[p * 3 + 2] = o2;
        }
        __syncwarp();  // stage/meta reuse across tiles
    }
}

extern "C" void kernel_launch(void *const *d_in, const int *in_sizes, int n_in,
                              void *d_out, int out_size)
{
    const float *pos = (const float *)d_in[0];
    const float *dir = (const float *)d_in[1];
    const float *pos_grid = (const float *)d_in[2];
    const float *dir_grid = (const float *)d_in[3];

    cudaMemcpyToSymbolAsync(cEnc, d_in[4], 8 * sizeof(float), 0, cudaMemcpyDeviceToDevice, 0);
    cudaMemcpyToSymbolAsync(cEnc, d_in[5], 4 * sizeof(float), 8 * sizeof(float), cudaMemcpyDeviceToDevice, 0);
    cudaMemcpyToSymbolAsync(cEnc, d_in[6], 12 * sizeof(float), 12 * sizeof(float), cudaMemcpyDeviceToDevice, 0);
    cudaMemcpyToSymbolAsync(cEnc, d_in[7], 3 * sizeof(float), 24 * sizeof(float), cudaMemcpyDeviceToDevice, 0);
    cudaMemcpyToSymbolAsync(cW3, d_in[12], 16 * 8 * sizeof(float), 0, cudaMemcpyDeviceToDevice, 0);
    cudaMemcpyToSymbolAsync(cB3, d_in[13], 8 * sizeof(float), 0, cudaMemcpyDeviceToDevice, 0);
    cudaMemcpyToSymbolAsync(cW4, d_in[14], 8 * 3 * sizeof(float), 0, cudaMemcpyDeviceToDevice, 0);
    cudaMemcpyToSymbolAsync(cB4, d_in[15], 3 * sizeof(float), 0, cudaMemcpyDeviceToDevice, 0);

    // pre-convert grids to bf16 (2*524288 u64 words, 256 thr/blk)
    convert_grids<<<4096, 256>>>(pos_grid, dir_grid);

    cudaFuncSetAttribute(gridnet_fused16, cudaFuncAttributeMaxDynamicSharedMemorySize, DYN_BYTES);

    float *out = (float *)d_out;
    int n = in_sizes[0] / 2;
    int ntiles = (n + 127) / 128;
    int blocks = 148 * 4;
    if (blocks > ntiles) blocks = ntiles;
    gridnet_fused16<<<blocks, 128, DYN_BYTES>>>(
        pos, dir,
        (const float *)d_in[8], (const float *)d_in[9],
        (const float *)d_in[10], (const float *)d_in[11],
        out, n, ntiles);
}

// round 11
// speedup vs baseline: 4.2243x; 1.0581x over previous
#include <cuda_runtime.h>
#include <stdint.h>

typedef unsigned long long u64;
typedef unsigned int u32;

// ---------------- cmem: small uniform-read constants ----------------
__constant__ __align__(16) float cW3[16 * 8];
__constant__ __align__(16) float cW4[8 * 3];
__constant__ __align__(16) float cB3[8];
__constant__ __align__(16) float cB4[3];
__constant__ __align__(16) float cEnc[27];

// fp16-converted grids: [2][256*256*16 u32 words] (each word = 2 features)
__device__ __align__(16) u32 g_f16[2 * 1048576];

// ---------------- dyn smem layout (u32 word offsets) ----------------
#define OFF_W1T 0            // [n=64][36] f16x2 words (k2 0..31 used)
#define OFF_W2T 2304         // [n=16][36]
#define OFF_B1 2880          // 64 f32
#define OFF_B2 2944          // 16 f32
#define META_V2_OFF 740      // ulonglong2 index (byte 11840); [warp][pair=4][33]
#define OFF_SX 5072          // feature / H2 stage: 4 warps x 32 rows x 32 words
#define DYN_BYTES 36864

// ---------------- helpers ----------------
static __device__ __forceinline__ u64 pack2(float lo, float hi) {
    u64 r; asm("mov.b64 %0, {%1, %2};" : "=l"(r) : "f"(lo), "f"(hi)); return r;
}
static __device__ __forceinline__ float2 unpack2(u64 v) {
    float2 f; asm("mov.b64 {%0, %1}, %2;" : "=f"(f.x), "=f"(f.y) : "l"(v)); return f;
}
static __device__ __forceinline__ void fma2(u64 &d, u64 a, u64 b) {
    asm("fma.rn.f32x2 %0, %1, %2, %0;" : "+l"(d) : "l"(a), "l"(b));
}
// pack two f32 into f16x2: lo -> bits[15:0], hi -> bits[31:16]
static __device__ __forceinline__ u32 packh2(float lo, float hi) {
    u32 d; asm("cvt.rn.f16x2.f32 %0, %1, %2;" : "=r"(d) : "f"(hi), "f"(lo)); return d;
}
static __device__ __forceinline__ u32 hfma2(u32 a, u32 b, u32 c) {
    u32 d; asm("fma.rn.f16x2 %0, %1, %2, %3;" : "=r"(d) : "r"(a), "r"(b), "r"(c)); return d;
}
static __device__ __forceinline__ void mma_f16(float *d, u32 a0, u32 a1, u32 a2, u32 a3,
                                               u32 b0, u32 b1) {
    asm("mma.sync.aligned.m16n8k16.row.col.f32.f16.f16.f32 "
        "{%0,%1,%2,%3},{%4,%5,%6,%7},{%8,%9},{%0,%1,%2,%3};"
        : "+f"(d[0]), "+f"(d[1]), "+f"(d[2]), "+f"(d[3])
        : "r"(a0), "r"(a1), "r"(a2), "r"(a3), "r"(b0), "r"(b1));
}
static __device__ __forceinline__ float leaky(float x) { return fmaxf(x, 0.01f * x); }
static __device__ __forceinline__ float sigmoidf(float x) { return 1.0f / (1.0f + __expf(-x)); }
static __device__ __forceinline__ float tanh_fast(float x) {
    return fmaf(2.0f, sigmoidf(2.0f * x), -1.0f);
}
static __device__ __forceinline__ void encode(float i0, float i1, float &x, float &y) {
    float h[4];
#pragma unroll
    for (int j = 0; j < 4; j++)
        h[j] = tanh_fast(fmaf(i0, cEnc[j], fmaf(i1, cEnc[4 + j], cEnc[8 + j])));
    float z0 = cEnc[24], z1 = cEnc[25];
#pragma unroll
    for (int j = 0; j < 4; j++) {
        z0 = fmaf(h[j], cEnc[12 + j * 3 + 0], z0);
        z1 = fmaf(h[j], cEnc[12 + j * 3 + 1], z1);
    }
    x = sigmoidf(z0) * 255.0f;
    y = sigmoidf(z1) * 255.0f;
}

// ---------------- grid pre-conversion: fp32 -> fp16x2 ----------------
__global__ void __launch_bounds__(256) convert_grids(
    const float *__restrict__ g0, const float *__restrict__ g1)
{
    int i = blockIdx.x * 256 + threadIdx.x;  // one float4 -> one u64
    const float *src = (i < 524288) ? g0 : g1;
    int j = i & 524287;
    float4 v = __ldg((const float4 *)src + j);
    u64 w = (u64)packh2(v.x, v.y) | ((u64)packh2(v.z, v.w) << 32);
    *((u64 *)g_f16 + i) = w;
}

// ---------------- main kernel ----------------
__global__ void __launch_bounds__(128, 4) gridnet_h16(
    const float *__restrict__ pos, const float *__restrict__ dir,
    const float *__restrict__ fc_w1, const float *__restrict__ fc_b1,
    const float *__restrict__ fc_w2, const float *__restrict__ fc_b2,
    float *__restrict__ out, int n, int ntiles)
{
    extern __shared__ __align__(16) char smraw[];
    u32 *sm = (u32 *)smraw;
    float *smf = (float *)smraw;

    const int tid = threadIdx.x;
    const int warp = tid >> 5, lane = tid & 31;
    const int grp = lane >> 3, f = lane & 7;   // loader roles
    const int r = lane >> 2, c = lane & 3;     // mma fragment roles

    // ---- stage weights once per CTA (f16x2 transposed [n][k2])
    for (int i = tid; i < 64 * 36; i += 128) {
        int nn = i / 36, k2 = i % 36;
        u32 v = 0;
        if (k2 < 32) v = packh2(fc_w1[(2 * k2) * 64 + nn], fc_w1[(2 * k2 + 1) * 64 + nn]);
        sm[OFF_W1T + i] = v;
    }
    for (int i = tid; i < 16 * 36; i += 128) {
        int nn = i / 36, k2 = i % 36;
        u32 v = 0;
        if (k2 < 32) v = packh2(fc_w2[(2 * k2) * 16 + nn], fc_w2[(2 * k2 + 1) * 16 + nn]);
        sm[OFF_W2T + i] = v;
    }
    if (tid < 64) smf[OFF_B1 + tid] = fc_b1[tid];
    if (tid < 16) smf[OFF_B2 + tid] = fc_b2[tid];
    __syncthreads();

    u32 *sx = sm + OFF_SX + warp * 1024;
    float *sxf = (float *)sx;
    ulonglong2 *mw = (ulonglong2 *)smraw + META_V2_OFF + warp * 132;  // [pair=4][33]

    const int rb0 = r * 32, rb1 = (r + 8) * 32, rb2 = (r + 16) * 32, rb3 = (r + 24) * 32;

    // prefetch first tile's coords
    int tile = blockIdx.x;
    float2 pco, dco;
    {
        int pc0 = min(tile * 128 + warp * 32 + lane, n - 1);
        pco = *(const float2 *)(pos + 2 * pc0);
        dco = *(const float2 *)(dir + 2 * pc0);
    }

    for (; tile < ntiles; tile += gridDim.x) {
        const int p = tile * 128 + warp * 32 + lane;
        float2 pcur = pco, dcur = dco;
        int tnext = tile + gridDim.x;
        if (tnext < ntiles) {
            int pcn = min(tnext * 128 + warp * 32 + lane, n - 1);
            pco = *(const float2 *)(pos + 2 * pcn);
            dco = *(const float2 *)(dir + 2 * pcn);
        }

        // ===== owner: encode -> corner metadata (offset | fp16x2 blend weight) =====
        {
            float gx[2], gy[2];
            encode(pcur.x, pcur.y, gx[0], gy[0]);
            encode(dcur.x, dcur.y, gx[1], gy[1]);
#pragma unroll
            for (int g = 0; g < 2; g++) {
                float x = gx[g], y = gy[g];
                int x0 = min((int)x, 255), y0 = min((int)y, 255);
                float xf = x - (float)x0, yf = y - (float)y0;
                int x1 = min(x0 + 1, 255), y1 = min(y0 + 1, 255);
                u32 o0 = (u32)(y0 * 256 + x0) * 64u;
                u32 o1 = (u32)(y0 * 256 + x1) * 64u;
                u32 o2 = (u32)(y1 * 256 + x0) * 64u;
                u32 o3 = (u32)(y1 * 256 + x1) * 64u;
                float w0 = (1.0f - xf) * (1.0f - yf);
                float w1 = xf * (1.0f - yf);
                float w2 = (1.0f - xf) * yf;
                float w3 = xf * yf;
                u64 m0 = (u64)o0 | ((u64)packh2(w0, w0) << 32);
                u64 m1 = (u64)o1 | ((u64)packh2(w1, w1) << 32);
                u64 m2 = (u64)o2 | ((u64)packh2(w2, w2) << 32);
                u64 m3 = (u64)o3 | ((u64)packh2(w3, w3) << 32);
                mw[(g * 2 + 0) * 33 + lane] = make_ulonglong2(m0, m1);
                mw[(g * 2 + 1) * 33 + lane] = make_ulonglong2(m2, m3);
            }
        }
        __syncwarp();

        // ===== loader: coop gather + fp16x2 blend -> rotated stage (no repack) =====
#pragma unroll 1
        for (int g = 0; g < 2; g++) {
            const char *gbase = (const char *)(g_f16 + (u32)g * 1048576u);
#pragma unroll
            for (int i = 0; i < 8; i++) {
                int row = i * 4 + grp;
                ulonglong2 mp0 = mw[(g * 2 + 0) * 33 + row];
                ulonglong2 mp1 = mw[(g * 2 + 1) * 33 + row];
                u32 acc01 = 0, acc23 = 0;
#pragma unroll
                for (int cc = 0; cc < 4; cc++) {
                    u64 m = (cc == 0) ? mp0.x : (cc == 1) ? mp0.y : (cc == 2) ? mp1.x : mp1.y;
                    u32 off = (u32)m;
                    u32 wb = (u32)(m >> 32);
                    u64 vw = __ldg((const u64 *)(gbase + off) + f);
                    acc01 = hfma2((u32)vw, wb, acc01);
                    acc23 = hfma2((u32)(vw >> 32), wb, acc23);
                }
                int k2 = g * 16 + 2 * f;
                int word = row * 32 + ((k2 + 4 * row) & 31);
                *(u64 *)&sx[word] = (u64)acc01 | ((u64)acc23 << 32);
            }
        }
        __syncwarp();

        // ===== FC1 + FC2 fused (fp16 MMA): D1-frags feed FC2 A-frags in registers =====
        float d2[16];
#pragma unroll
        for (int q = 0; q < 16; q++) d2[q] = 0.0f;

#pragma unroll 1
        for (int half = 0; half < 2; half++) {
            float d1[32];
#pragma unroll
            for (int q = 0; q < 32; q++) d1[q] = 0.0f;
#pragma unroll
            for (int kt = 0; kt < 4; kt++) {
                int rot0 = (8 * kt + c + 4 * r) & 31;
                int rot1 = (rot0 + 4) & 31;
                u32 a00 = sx[rb0 + rot0], a01 = sx[rb1 + rot0];
                u32 a02 = sx[rb0 + rot1], a03 = sx[rb1 + rot1];
                u32 a10 = sx[rb2 + rot0], a11 = sx[rb3 + rot0];
                u32 a12 = sx[rb2 + rot1], a13 = sx[rb3 + rot1];
#pragma unroll
                for (int ntp = 0; ntp < 4; ntp++) {
                    int nt = half * 4 + ntp;
                    u32 b0 = sm[OFF_W1T + (8 * nt + r) * 36 + 8 * kt + c];
                    u32 b1 = sm[OFF_W1T + (8 * nt + r) * 36 + 8 * kt + c + 4];
                    mma_f16(d1 + ntp * 8, a00, a01, a02, a03, b0, b1);
                    mma_f16(d1 + ntp * 8 + 4, a10, a11, a12, a13, b0, b1);
                }
            }
            // FC2 partial: A-frags straight from d1 regs (same fragment layout)
#pragma unroll
            for (int ktp = 0; ktp < 2; ktp++) {
                const float *dA0 = d1 + (2 * ktp) * 8;
                const float *dA1 = d1 + (2 * ktp + 1) * 8;
                int ntA0 = half * 4 + 2 * ktp, ntA1 = ntA0 + 1;
                float blo0 = smf[OFF_B1 + 8 * ntA0 + 2 * c];
                float bhi0 = smf[OFF_B1 + 8 * ntA0 + 2 * c + 1];
                float blo1 = smf[OFF_B1 + 8 * ntA1 + 2 * c];
                float bhi1 = smf[OFF_B1 + 8 * ntA1 + 2 * c + 1];
                u32 a0 = packh2(leaky(dA0[0] + blo0), leaky(dA0[1] + bhi0));
                u32 a1 = packh2(leaky(dA0[2] + blo0), leaky(dA0[3] + bhi0));
                u32 a2 = packh2(leaky(dA1[0] + blo1), leaky(dA1[1] + bhi1));
                u32 a3 = packh2(leaky(dA1[2] + blo1), leaky(dA1[3] + bhi1));
                u32 a10 = packh2(leaky(dA0[4] + blo0), leaky(dA0[5] + bhi0));
                u32 a11 = packh2(leaky(dA0[6] + blo0), leaky(dA0[7] + bhi0));
                u32 a12 = packh2(leaky(dA1[4] + blo1), leaky(dA1[5] + bhi1));
                u32 a13 = packh2(leaky(dA1[6] + blo1), leaky(dA1[7] + bhi1));
                int kt2 = half * 2 + ktp;
#pragma unroll
                for (int nt2 = 0; nt2 < 2; nt2++) {
                    u32 b0 = sm[OFF_W2T + (8 * nt2 + r) * 36 + 8 * kt2 + c];
                    u32 b1 = sm[OFF_W2T + (8 * nt2 + r) * 36 + 8 * kt2 + c + 4];
                    mma_f16(d2 + nt2 * 8, a0, a1, a2, a3, b0, b1);
                    mma_f16(d2 + nt2 * 8 + 4, a10, a11, a12, a13, b0, b1);
                }
            }
        }
        __syncwarp();

        // ===== H2 = leaky(D2 + b2) -> f32 restage into sx (rotated cols 0..15) =====
#pragma unroll
        for (int nt = 0; nt < 2; nt++) {
            float blo = smf[OFF_B2 + 8 * nt + 2 * c];
            float bhi = smf[OFF_B2 + 8 * nt + 2 * c + 1];
            const float *dd = d2 + nt * 8;
            int rot = (8 * nt + 2 * c + 4 * r) & 31;
            *(u64 *)&sxf[rb0 + rot] = pack2(leaky(dd[0] + blo), leaky(dd[1] + bhi));
            *(u64 *)&sxf[rb1 + rot] = pack2(leaky(dd[2] + blo), leaky(dd[3] + bhi));
            *(u64 *)&sxf[rb2 + rot] = pack2(leaky(dd[4] + blo), leaky(dd[5] + bhi));
            *(u64 *)&sxf[rb3 + rot] = pack2(leaky(dd[6] + blo), leaky(dd[7] + bhi));
        }
        __syncwarp();

        // ===== head: FC3 (16->8, cmem uniform) + FC4 + sigmoid*255 =====
        float a2[16];
#pragma unroll
        for (int q = 0; q < 4; q++) {
            float4 v = *(const float4 *)&sxf[lane * 32 + ((4 * q + 4 * lane) & 31)];
            a2[4 * q + 0] = v.x;
            a2[4 * q + 1] = v.y;
            a2[4 * q + 2] = v.z;
            a2[4 * q + 3] = v.w;
        }
        u64 h3[4];
#pragma unroll
        for (int q = 0; q < 4; q++) h3[q] = pack2(cB3[2 * q], cB3[2 * q + 1]);
#pragma unroll
        for (int j = 0; j < 16; j++) {
            float a = a2[j];
            u64 av = pack2(a, a);
            const ulonglong2 *w = (const ulonglong2 *)(cW3 + j * 8);
            ulonglong2 w01 = w[0], w23 = w[1];
            fma2(h3[0], av, w01.x);
            fma2(h3[1], av, w01.y);
            fma2(h3[2], av, w23.x);
            fma2(h3[3], av, w23.y);
        }
        float o0 = cB4[0], o1 = cB4[1], o2 = cB4[2];
#pragma unroll
        for (int q = 0; q < 4; q++) {
            float2 v = unpack2(h3[q]);
            float a0 = leaky(v.x), a1 = leaky(v.y);
            int i0 = 2 * q, i1 = 2 * q + 1;
            o0 = fmaf(a0, cW4[i0 * 3 + 0], o0);
            o1 = fmaf(a0, cW4[i0 * 3 + 1], o1);
            o2 = fmaf(a0, cW4[i0 * 3 + 2], o2);
            o0 = fmaf(a1, cW4[i1 * 3 + 0], o0);
            o1 = fmaf(a1, cW4[i1 * 3 + 1], o1);
            o2 = fmaf(a1, cW4[i1 * 3 + 2], o2);
        }
        o0 = sigmoidf(leaky(o0)) * 255.0f;
        o1 = sigmoidf(leaky(o1)) * 255.0f;
        o2 = sigmoidf(leaky(o2)) * 255.0f;

        if (p < n) {
            out[p * 3 + 0] = o0;
            out[p * 3 + 1] = o1;
            out[p * 3 + 2] = o2;
        }
        __syncwarp();  // stage/meta reuse across tiles
    }
}

extern "C" void kernel_launch(void *const *d_in, const int *in_sizes, int n_in,
                              void *d_out, int out_size)
{
    const float *pos = (const float *)d_in[0];
    const float *dir = (const float *)d_in[1];
    const float *pos_grid = (const float *)d_in[2];
    const float *dir_grid = (const float *)d_in[3];

    cudaMemcpyToSymbolAsync(cEnc, d_in[4], 8 * sizeof(float), 0, cudaMemcpyDeviceToDevice, 0);
    cudaMemcpyToSymbolAsync(cEnc, d_in[5], 4 * sizeof(float), 8 * sizeof(float), cudaMemcpyDeviceToDevice, 0);
    cudaMemcpyToSymbolAsync(cEnc, d_in[6], 12 * sizeof(float), 12 * sizeof(float), cudaMemcpyDeviceToDevice, 0);
    cudaMemcpyToSymbolAsync(cEnc, d_in[7], 3 * sizeof(float), 24 * sizeof(float), cudaMemcpyDeviceToDevice, 0);
    cudaMemcpyToSymbolAsync(cW3, d_in[12], 16 * 8 * sizeof(float), 0, cudaMemcpyDeviceToDevice, 0);
    cudaMemcpyToSymbolAsync(cB3, d_in[13], 8 * sizeof(float), 0, cudaMemcpyDeviceToDevice, 0);
    cudaMemcpyToSymbolAsync(cW4, d_in[14], 8 * 3 * sizeof(float), 0, cudaMemcpyDeviceToDevice, 0);
    cudaMemcpyToSymbolAsync(cB4, d_in[15], 3 * sizeof(float), 0, cudaMemcpyDeviceToDevice, 0);

    // pre-convert grids to fp16 (2*524288 u64 words, 256 thr/blk)
    convert_grids<<<4096, 256>>>(pos_grid, dir_grid);

    cudaFuncSetAttribute(gridnet_h16, cudaFuncAttributeMaxDynamicSharedMemorySize, DYN_BYTES);

    float *out = (float *)d_out;
    int n = in_sizes[0] / 2;
    int ntiles = (n + 127) / 128;
    int blocks = 148 * 4;
    if (blocks > ntiles) blocks = ntiles;
    gridnet_h16<<<blocks, 128, DYN_BYTES>>>(
        pos, dir,
        (const float *)d_in[8], (const float *)d_in[9],
        (const float *)d_in[10], (const float *)d_in[11],
        out, n, ntiles);
}

// round 12
// speedup vs baseline: 5.0599x; 1.1978x over previous
#include <cuda_runtime.h>
#include <stdint.h>

typedef unsigned long long u64;
typedef unsigned int u32;

// ---------------- cmem: small uniform-read constants ----------------
__constant__ __align__(16) float cW3[16 * 8];
__constant__ __align__(16) float cW4[8 * 3];
__constant__ __align__(16) float cB3[8];
__constant__ __align__(16) float cB4[3];
__constant__ __align__(16) float cEnc[27];

// fp16-converted grids: [2][256*256*16 u32 words]
__device__ __align__(16) u32 g_f16[2 * 1048576];

// ---------------- dyn smem layout (byte offsets) ----------------
#define OFFB_W1P 0        // [n=64][16] u64 pairs (b0,b1), row stride 20 u64
#define OFFB_W2P 10240    // [n=16][16] u64 pairs, stride 20 u64
#define OFFB_B1 12800     // 64 f32
#define OFFB_B2 13056     // 16 f32
#define OFFB_META 13120   // [warp][pair=4][33] ulonglong2
#define OFFB_STAGE 21568  // [warp][32 rows][32 words] u32
#define DYN_BYTES 37952

// stage rotation (words, multiple of 4): conflict-free for STS.128 writes,
// LDSM 8-row reads, H2 restage and head readback simultaneously.
#define ROT(row) ((((row) & 1) << 4) | (((row) & 6) << 1))

// ---------------- helpers ----------------
static __device__ __forceinline__ u64 pack2(float lo, float hi) {
    u64 r; asm("mov.b64 %0, {%1, %2};" : "=l"(r) : "f"(lo), "f"(hi)); return r;
}
static __device__ __forceinline__ float2 unpack2(u64 v) {
    float2 f; asm("mov.b64 {%0, %1}, %2;" : "=f"(f.x), "=f"(f.y) : "l"(v)); return f;
}
static __device__ __forceinline__ void fma2(u64 &d, u64 a, u64 b) {
    asm("fma.rn.f32x2 %0, %1, %2, %0;" : "+l"(d) : "l"(a), "l"(b));
}
static __device__ __forceinline__ u32 packh2(float lo, float hi) {
    u32 d; asm("cvt.rn.f16x2.f32 %0, %1, %2;" : "=r"(d) : "f"(hi), "f"(lo)); return d;
}
static __device__ __forceinline__ u32 hfma2(u32 a, u32 b, u32 c) {
    u32 d; asm("fma.rn.f16x2 %0, %1, %2, %3;" : "=r"(d) : "r"(a), "r"(b), "r"(c)); return d;
}
static __device__ __forceinline__ void mma_f16(float *d, u32 a0, u32 a1, u32 a2, u32 a3,
                                               u32 b0, u32 b1) {
    asm("mma.sync.aligned.m16n8k16.row.col.f32.f16.f16.f32 "
        "{%0,%1,%2,%3},{%4,%5,%6,%7},{%8,%9},{%0,%1,%2,%3};"
        : "+f"(d[0]), "+f"(d[1]), "+f"(d[2]), "+f"(d[3])
        : "r"(a0), "r"(a1), "r"(a2), "r"(a3), "r"(b0), "r"(b1));
}
static __device__ __forceinline__ void ldsm4(u32 &r0, u32 &r1, u32 &r2, u32 &r3, u32 addr) {
    asm volatile("ldmatrix.sync.aligned.m8n8.x4.shared.b16 {%0,%1,%2,%3}, [%4];"
                 : "=r"(r0), "=r"(r1), "=r"(r2), "=r"(r3) : "r"(addr));
}
static __device__ __forceinline__ u32 smem_u32(const void *p) {
    u32 a;
    asm("{ .reg .u64 t; cvta.to.shared.u64 t, %1; cvt.u32.u64 %0, t; }" : "=r"(a) : "l"(p));
    return a;
}
static __device__ __forceinline__ void sts128u(u32 addr, u32 a, u32 b, u32 c, u32 d) {
    asm volatile("st.shared.v4.u32 [%0], {%1,%2,%3,%4};"
                 :: "r"(addr), "r"(a), "r"(b), "r"(c), "r"(d) : "memory");
}
static __device__ __forceinline__ float leaky(float x) { return fmaxf(x, 0.01f * x); }
static __device__ __forceinline__ float sigmoidf(float x) { return 1.0f / (1.0f + __expf(-x)); }
static __device__ __forceinline__ float tanh_fast(float x) {
    return fmaf(2.0f, sigmoidf(2.0f * x), -1.0f);
}
static __device__ __forceinline__ void encode(float i0, float i1, float &x, float &y) {
    float h[4];
#pragma unroll
    for (int j = 0; j < 4; j++)
        h[j] = tanh_fast(fmaf(i0, cEnc[j], fmaf(i1, cEnc[4 + j], cEnc[8 + j])));
    float z0 = cEnc[24], z1 = cEnc[25];
#pragma unroll
    for (int j = 0; j < 4; j++) {
        z0 = fmaf(h[j], cEnc[12 + j * 3 + 0], z0);
        z1 = fmaf(h[j], cEnc[12 + j * 3 + 1], z1);
    }
    x = sigmoidf(z0) * 255.0f;
    y = sigmoidf(z1) * 255.0f;
}

// ---------------- grid pre-conversion: fp32 -> fp16x2 ----------------
__global__ void __launch_bounds__(256) convert_grids(
    const float *__restrict__ g0, const float *__restrict__ g1)
{
    int i = blockIdx.x * 256 + threadIdx.x;
    const float *src = (i < 524288) ? g0 : g1;
    int j = i & 524287;
    float4 v = __ldg((const float4 *)src + j);
    u64 w = (u64)packh2(v.x, v.y) | ((u64)packh2(v.z, v.w) << 32);
    *((u64 *)g_f16 + i) = w;
}

// ---------------- main kernel ----------------
__global__ void __launch_bounds__(128, 4) gridnet_ldsm(
    const float *__restrict__ pos, const float *__restrict__ dir,
    const float *__restrict__ fc_w1, const float *__restrict__ fc_b1,
    const float *__restrict__ fc_w2, const float *__restrict__ fc_b2,
    float *__restrict__ out, int n, int ntiles)
{
    extern __shared__ __align__(16) char smraw[];
    float *smf = (float *)smraw;

    const int tid = threadIdx.x;
    const int warp = tid >> 5, lane = tid & 31;
    const int rowgrp = lane >> 2, sub = lane & 3;  // loader roles (4 lanes/row)
    const int r = lane >> 2, c = lane & 3;         // mma fragment roles

    // ---- stage weights once per CTA: u64-packed (b0,b1) pairs, stride 20 u64
    for (int i = tid; i < 64 * 16; i += 128) {
        int nn = i >> 4, idx = i & 15;  // idx = 4*kt + c
        int kt = idx >> 2, cc = idx & 3;
        int w0k2 = 8 * kt + cc, w1k2 = w0k2 + 4;
        u32 lo = packh2(fc_w1[(2 * w0k2) * 64 + nn], fc_w1[(2 * w0k2 + 1) * 64 + nn]);
        u32 hi = packh2(fc_w1[(2 * w1k2) * 64 + nn], fc_w1[(2 * w1k2 + 1) * 64 + nn]);
        *(u64 *)(smraw + OFFB_W1P + ((u32)(nn * 20 + idx) * 8)) = (u64)lo | ((u64)hi << 32);
    }
    for (int i = tid; i < 16 * 16; i += 128) {
        int nn = i >> 4, idx = i & 15;
        int kt = idx >> 2, cc = idx & 3;
        int w0k2 = 8 * kt + cc, w1k2 = w0k2 + 4;
        u32 lo = packh2(fc_w2[(2 * w0k2) * 16 + nn], fc_w2[(2 * w0k2 + 1) * 16 + nn]);
        u32 hi = packh2(fc_w2[(2 * w1k2) * 16 + nn], fc_w2[(2 * w1k2 + 1) * 16 + nn]);
        *(u64 *)(smraw + OFFB_W2P + ((u32)(nn * 20 + idx) * 8)) = (u64)lo | ((u64)hi << 32);
    }
    if (tid < 64) *(float *)(smraw + OFFB_B1 + tid * 4) = fc_b1[tid];
    if (tid < 16) *(float *)(smraw + OFFB_B2 + tid * 4) = fc_b2[tid];
    __syncthreads();

    const float *sB1 = (const float *)(smraw + OFFB_B1);
    const float *sB2 = (const float *)(smraw + OFFB_B2);
    u32 *sx = (u32 *)(smraw + OFFB_STAGE) + warp * 1024;
    float *sxf = (float *)sx;
    const u32 sx_addr = smem_u32(sx);
    ulonglong2 *mw = (ulonglong2 *)(smraw + OFFB_META) + warp * 132;  // [pair=4][33]

    // ldmatrix role precompute
    const int mi = lane >> 3, rr = lane & 7;
    const int rotA = ROT(rr);
    const u32 baseA = sx_addr + (u32)(((mi & 1) * 8 + rr) * 128);
    const u32 baseB = baseA + 16 * 128;
    const int khalf = (mi >> 1) * 4;

    // prefetch first tile's coords
    int tile = blockIdx.x;
    float2 pco, dco;
    {
        int pc0 = min(tile * 128 + warp * 32 + lane, n - 1);
        pco = *(const float2 *)(pos + 2 * pc0);
        dco = *(const float2 *)(dir + 2 * pc0);
    }

    for (; tile < ntiles; tile += gridDim.x) {
        const int p = tile * 128 + warp * 32 + lane;
        float2 pcur = pco, dcur = dco;
        int tnext = tile + gridDim.x;
        if (tnext < ntiles) {
            int pcn = min(tnext * 128 + warp * 32 + lane, n - 1);
            pco = *(const float2 *)(pos + 2 * pcn);
            dco = *(const float2 *)(dir + 2 * pcn);
        }

        // ===== owner: encode -> corner metadata (offset | fp16x2 weight) =====
        {
            float gx[2], gy[2];
            encode(pcur.x, pcur.y, gx[0], gy[0]);
            encode(dcur.x, dcur.y, gx[1], gy[1]);
#pragma unroll
            for (int g = 0; g < 2; g++) {
                float x = gx[g], y = gy[g];
                int x0 = min((int)x, 255), y0 = min((int)y, 255);
                float xf = x - (float)x0, yf = y - (float)y0;
                int x1 = min(x0 + 1, 255), y1 = min(y0 + 1, 255);
                u32 o0 = (u32)(y0 * 256 + x0) * 64u;
                u32 o1 = (u32)(y0 * 256 + x1) * 64u;
                u32 o2 = (u32)(y1 * 256 + x0) * 64u;
                u32 o3 = (u32)(y1 * 256 + x1) * 64u;
                float w0 = (1.0f - xf) * (1.0f - yf);
                float w1 = xf * (1.0f - yf);
                float w2 = (1.0f - xf) * yf;
                float w3 = xf * yf;
                u64 m0 = (u64)o0 | ((u64)packh2(w0, w0) << 32);
                u64 m1 = (u64)o1 | ((u64)packh2(w1, w1) << 32);
                u64 m2 = (u64)o2 | ((u64)packh2(w2, w2) << 32);
                u64 m3 = (u64)o3 | ((u64)packh2(w3, w3) << 32);
                mw[(g * 2 + 0) * 33 + lane] = make_ulonglong2(m0, m1);
                mw[(g * 2 + 1) * 33 + lane] = make_ulonglong2(m2, m3);
            }
        }
        __syncwarp();

        // ===== loader: 4 lanes/row, LDG.128 gather + fp16x2 blend -> rotated stage =====
#pragma unroll 1
        for (int g = 0; g < 2; g++) {
            const char *gbase = (const char *)(g_f16 + (u32)g * 1048576u);
#pragma unroll
            for (int i = 0; i < 4; i++) {
                int row = i * 8 + rowgrp;
                ulonglong2 mp0 = mw[(g * 2 + 0) * 33 + row];
                ulonglong2 mp1 = mw[(g * 2 + 1) * 33 + row];
                u32 a0 = 0, a1 = 0, a2 = 0, a3 = 0;
#pragma unroll
                for (int cc = 0; cc < 4; cc++) {
                    u64 m = (cc == 0) ? mp0.x : (cc == 1) ? mp0.y : (cc == 2) ? mp1.x : mp1.y;
                    u32 wb = (u32)(m >> 32);
                    uint4 v = __ldg((const uint4 *)(gbase + (u32)m) + sub);
                    a0 = hfma2(v.x, wb, a0);
                    a1 = hfma2(v.y, wb, a1);
                    a2 = hfma2(v.z, wb, a2);
                    a3 = hfma2(v.w, wb, a3);
                }
                int word = row * 32 + ((g * 16 + 4 * sub + ROT(row)) & 31);
                sts128u(sx_addr + (u32)(word * 4), a0, a1, a2, a3);
            }
        }
        __syncwarp();

        // ===== FC1 + FC2 fused: ldmatrix A-frags, u64 B-frags =====
        float d2[16];
#pragma unroll
        for (int q = 0; q < 16; q++) d2[q] = 0.0f;

#pragma unroll 1
        for (int half = 0; half < 2; half++) {
            float d1[32];
#pragma unroll
            for (int q = 0; q < 32; q++) d1[q] = 0.0f;
#pragma unroll
            for (int kt = 0; kt < 4; kt++) {
                u32 wo = (u32)(((8 * kt + khalf + rotA) & 31) * 4);
                u32 a00, a01, a02, a03, a10, a11, a12, a13;
                ldsm4(a00, a01, a02, a03, baseA + wo);
                ldsm4(a10, a11, a12, a13, baseB + wo);
#pragma unroll
                for (int ntp = 0; ntp < 4; ntp++) {
                    int nt = half * 4 + ntp;
                    u64 bb = *(const u64 *)(smraw + OFFB_W1P +
                                            (u32)(((8 * nt + r) * 20 + 4 * kt + c) * 8));
                    u32 b0 = (u32)bb, b1 = (u32)(bb >> 32);
                    mma_f16(d1 + ntp * 8, a00, a01, a02, a03, b0, b1);
                    mma_f16(d1 + ntp * 8 + 4, a10, a11, a12, a13, b0, b1);
                }
            }
            // FC2 partial: A-frags straight from d1 regs
#pragma unroll
            for (int ktp = 0; ktp < 2; ktp++) {
                const float *dA0 = d1 + (2 * ktp) * 8;
                const float *dA1 = d1 + (2 * ktp + 1) * 8;
                int ntA0 = half * 4 + 2 * ktp, ntA1 = ntA0 + 1;
                float blo0 = sB1[8 * ntA0 + 2 * c];
                float bhi0 = sB1[8 * ntA0 + 2 * c + 1];
                float blo1 = sB1[8 * ntA1 + 2 * c];
                float bhi1 = sB1[8 * ntA1 + 2 * c + 1];
                u32 a0 = packh2(leaky(dA0[0] + blo0), leaky(dA0[1] + bhi0));
                u32 a1 = packh2(leaky(dA0[2] + blo0), leaky(dA0[3] + bhi0));
                u32 a2 = packh2(leaky(dA1[0] + blo1), leaky(dA1[1] + bhi1));
                u32 a3 = packh2(leaky(dA1[2] + blo1), leaky(dA1[3] + bhi1));
                u32 a10 = packh2(leaky(dA0[4] + blo0), leaky(dA0[5] + bhi0));
                u32 a11 = packh2(leaky(dA0[6] + blo0), leaky(dA0[7] + bhi0));
                u32 a12 = packh2(leaky(dA1[4] + blo1), leaky(dA1[5] + bhi1));
                u32 a13 = packh2(leaky(dA1[6] + blo1), leaky(dA1[7] + bhi1));
                int kt2 = half * 2 + ktp;
#pragma unroll
                for (int nt2 = 0; nt2 < 2; nt2++) {
                    u64 bb = *(const u64 *)(smraw + OFFB_W2P +
                                            (u32)(((8 * nt2 + r) * 20 + 4 * kt2 + c) * 8));
                    u32 b0 = (u32)bb, b1 = (u32)(bb >> 32);
                    mma_f16(d2 + nt2 * 8, a0, a1, a2, a3, b0, b1);
                    mma_f16(d2 + nt2 * 8 + 4, a10, a11, a12, a13, b0, b1);
                }
            }
        }
        __syncwarp();

        // ===== H2 = leaky(D2 + b2) -> f32 restage (rotated) =====
        {
            int rotH = ROT(r);
#pragma unroll
            for (int nt = 0; nt < 2; nt++) {
                float blo = sB2[8 * nt + 2 * c];
                float bhi = sB2[8 * nt + 2 * c + 1];
                const float *dd = d2 + nt * 8;
                int wo = (8 * nt + 2 * c + rotH) & 31;
                *(u64 *)&sxf[(r) * 32 + wo] = pack2(leaky(dd[0] + blo), leaky(dd[1] + bhi));
                *(u64 *)&sxf[(r + 8) * 32 + wo] = pack2(leaky(dd[2] + blo), leaky(dd[3] + bhi));
                *(u64 *)&sxf[(r + 16) * 32 + wo] = pack2(leaky(dd[4] + blo), leaky(dd[5] + bhi));
                *(u64 *)&sxf[(r + 24) * 32 + wo] = pack2(leaky(dd[6] + blo), leaky(dd[7] + bhi));
            }
        }
        __syncwarp();

        // ===== head: FC3 (16->8, cmem uniform) + FC4 + sigmoid*255 =====
        float a2[16];
        {
            int rotL = ROT(lane);
#pragma unroll
            for (int q = 0; q < 4; q++) {
                float4 v = *(const float4 *)&sxf[lane * 32 + ((4 * q + rotL) & 31)];
                a2[4 * q + 0] = v.x;
                a2[4 * q + 1] = v.y;
                a2[4 * q + 2] = v.z;
                a2[4 * q + 3] = v.w;
            }
        }
        u64 h3[4];
#pragma unroll
        for (int q = 0; q < 4; q++) h3[q] = pack2(cB3[2 * q], cB3[2 * q + 1]);
#pragma unroll
        for (int j = 0; j < 16; j++) {
            float a = a2[j];
            u64 av = pack2(a, a);
            const ulonglong2 *w = (const ulonglong2 *)(cW3 + j * 8);
            ulonglong2 w01 = w[0], w23 = w[1];
            fma2(h3[0], av, w01.x);
            fma2(h3[1], av, w01.y);
            fma2(h3[2], av, w23.x);
            fma2(h3[3], av, w23.y);
        }
        float o0 = cB4[0], o1 = cB4[1], o2 = cB4[2];
#pragma unroll
        for (int q = 0; q < 4; q++) {
            float2 v = unpack2(h3[q]);
            float a0 = leaky(v.x), a1 = leaky(v.y);
            int i0 = 2 * q, i1 = 2 * q + 1;
            o0 = fmaf(a0, cW4[i0 * 3 + 0], o0);
            o1 = fmaf(a0, cW4[i0 * 3 + 1], o1);
            o2 = fmaf(a0, cW4[i0 * 3 + 2], o2);
            o0 = fmaf(a1, cW4[i1 * 3 + 0], o0);
            o1 = fmaf(a1, cW4[i1 * 3 + 1], o1);
            o2 = fmaf(a1, cW4[i1 * 3 + 2], o2);
        }
        o0 = sigmoidf(leaky(o0)) * 255.0f;
        o1 = sigmoidf(leaky(o1)) * 255.0f;
        o2 = sigmoidf(leaky(o2)) * 255.0f;

        if (p < n) {
            out[p * 3 + 0] = o0;
            out[p * 3 + 1] = o1;
            out[p * 3 + 2] = o2;
        }
        __syncwarp();  // stage/meta reuse across tiles
    }
}

extern "C" void kernel_launch(void *const *d_in, const int *in_sizes, int n_in,
                              void *d_out, int out_size)
{
    const float *pos = (const float *)d_in[0];
    const float *dir = (const float *)d_in[1];
    const float *pos_grid = (const float *)d_in[2];
    const float *dir_grid = (const float *)d_in[3];

    cudaMemcpyToSymbolAsync(cEnc, d_in[4], 8 * sizeof(float), 0, cudaMemcpyDeviceToDevice, 0);
    cudaMemcpyToSymbolAsync(cEnc, d_in[5], 4 * sizeof(float), 8 * sizeof(float), cudaMemcpyDeviceToDevice, 0);
    cudaMemcpyToSymbolAsync(cEnc, d_in[6], 12 * sizeof(float), 12 * sizeof(float), cudaMemcpyDeviceToDevice, 0);
    cudaMemcpyToSymbolAsync(cEnc, d_in[7], 3 * sizeof(float), 24 * sizeof(float), cudaMemcpyDeviceToDevice, 0);
    cudaMemcpyToSymbolAsync(cW3, d_in[12], 16 * 8 * sizeof(float), 0, cudaMemcpyDeviceToDevice, 0);
    cudaMemcpyToSymbolAsync(cB3, d_in[13], 8 * sizeof(float), 0, cudaMemcpyDeviceToDevice, 0);
    cudaMemcpyToSymbolAsync(cW4, d_in[14], 8 * 3 * sizeof(float), 0, cudaMemcpyDeviceToDevice, 0);
    cudaMemcpyToSymbolAsync(cB4, d_in[15], 3 * sizeof(float), 0, cudaMemcpyDeviceToDevice, 0);

    convert_grids<<<4096, 256>>>(pos_grid, dir_grid);

    cudaFuncSetAttribute(gridnet_ldsm, cudaFuncAttributeMaxDynamicSharedMemorySize, DYN_BYTES);

    float *out = (float *)d_out;
    int n = in_sizes[0] / 2;
    int ntiles = (n + 127) / 128;
    int blocks = 148 * 4;
    if (blocks > ntiles) blocks = ntiles;
    gridnet_ldsm<<<blocks, 128, DYN_BYTES>>>(
        pos, dir,
        (const float *)d_in[8], (const float *)d_in[9],
        (const float *)d_in[10], (const float *)d_in[11],
        out, n, ntiles);
}

// round 13
// speedup vs baseline: 5.2916x; 1.0458x over previous
#include <cuda_runtime.h>
#include <stdint.h>

typedef unsigned long long u64;
typedef unsigned int u32;

// ---------------- cmem: small uniform-read constants ----------------
__constant__ __align__(16) float cW3[16 * 8];
__constant__ __align__(16) float cW4[8 * 3];
__constant__ __align__(16) float cB3[8];
__constant__ __align__(16) float cB4[3];
__constant__ __align__(16) float cEnc[27];

// fp16-converted grids: [2][256*256*16 u32 words]
__device__ __align__(16) u32 g_f16[2 * 1048576];

// ---------------- dyn smem layout (byte offsets) ----------------
#define OFFB_W1P 0        // [n=64][16] u64 pairs (b0,b1), row stride 20 u64
#define OFFB_W2P 10240    // [n=16][16] u64 pairs, stride 20 u64
#define OFFB_B1 12800     // 64 f32
#define OFFB_B2 13056     // 16 f32
#define OFFB_META 13120   // [warp][32 rows][12 u32]  (8 used: g0c0..3, g1c0..3)
#define OFFB_STAGE 19264  // [warp][32 rows][32 words] u32
#define DYN_BYTES 35648

// stage rotation (words, multiple of 4): conflict-free for STS.128 writes,
// LDSM 8-row reads, H2 restage and head readback simultaneously.
#define ROT(row) ((((row) & 1) << 4) | (((row) & 6) << 1))

// ---------------- helpers ----------------
static __device__ __forceinline__ u64 pack2(float lo, float hi) {
    u64 r; asm("mov.b64 %0, {%1, %2};" : "=l"(r) : "f"(lo), "f"(hi)); return r;
}
static __device__ __forceinline__ float2 unpack2(u64 v) {
    float2 f; asm("mov.b64 {%0, %1}, %2;" : "=f"(f.x), "=f"(f.y) : "l"(v)); return f;
}
static __device__ __forceinline__ void fma2(u64 &d, u64 a, u64 b) {
    asm("fma.rn.f32x2 %0, %1, %2, %0;" : "+l"(d) : "l"(a), "l"(b));
}
static __device__ __forceinline__ u32 packh2(float lo, float hi) {
    u32 d; asm("cvt.rn.f16x2.f32 %0, %1, %2;" : "=r"(d) : "f"(hi), "f"(lo)); return d;
}
static __device__ __forceinline__ u32 hfma2(u32 a, u32 b, u32 c) {
    u32 d; asm("fma.rn.f16x2 %0, %1, %2, %3;" : "=r"(d) : "r"(a), "r"(b), "r"(c)); return d;
}
static __device__ __forceinline__ u32 prmt_hi2(u32 a) {  // [b3b2|b3b2]
    u32 d; asm("prmt.b32 %0, %1, %1, 0x3232;" : "=r"(d) : "r"(a)); return d;
}
static __device__ __forceinline__ void mma_f16(float *d, u32 a0, u32 a1, u32 a2, u32 a3,
                                               u32 b0, u32 b1) {
    asm("mma.sync.aligned.m16n8k16.row.col.f32.f16.f16.f32 "
        "{%0,%1,%2,%3},{%4,%5,%6,%7},{%8,%9},{%0,%1,%2,%3};"
        : "+f"(d[0]), "+f"(d[1]), "+f"(d[2]), "+f"(d[3])
        : "r"(a0), "r"(a1), "r"(a2), "r"(a3), "r"(b0), "r"(b1));
}
static __device__ __forceinline__ void ldsm4(u32 &r0, u32 &r1, u32 &r2, u32 &r3, u32 addr) {
    asm volatile("ldmatrix.sync.aligned.m8n8.x4.shared.b16 {%0,%1,%2,%3}, [%4];"
                 : "=r"(r0), "=r"(r1), "=r"(r2), "=r"(r3) : "r"(addr));
}
static __device__ __forceinline__ u32 smem_u32(const void *p) {
    u32 a;
    asm("{ .reg .u64 t; cvta.to.shared.u64 t, %1; cvt.u32.u64 %0, t; }" : "=r"(a) : "l"(p));
    return a;
}
static __device__ __forceinline__ void sts128u(u32 addr, u32 a, u32 b, u32 c, u32 d) {
    asm volatile("st.shared.v4.u32 [%0], {%1,%2,%3,%4};"
                 :: "r"(addr), "r"(a), "r"(b), "r"(c), "r"(d) : "memory");
}
static __device__ __forceinline__ float leaky(float x) { return fmaxf(x, 0.01f * x); }
static __device__ __forceinline__ float sigmoidf(float x) { return 1.0f / (1.0f + __expf(-x)); }
static __device__ __forceinline__ float tanh_fast(float x) {
    return fmaf(2.0f, sigmoidf(2.0f * x), -1.0f);
}
static __device__ __forceinline__ void encode(float i0, float i1, float &x, float &y) {
    float h[4];
#pragma unroll
    for (int j = 0; j < 4; j++)
        h[j] = tanh_fast(fmaf(i0, cEnc[j], fmaf(i1, cEnc[4 + j], cEnc[8 + j])));
    float z0 = cEnc[24], z1 = cEnc[25];
#pragma unroll
    for (int j = 0; j < 4; j++) {
        z0 = fmaf(h[j], cEnc[12 + j * 3 + 0], z0);
        z1 = fmaf(h[j], cEnc[12 + j * 3 + 1], z1);
    }
    x = sigmoidf(z0) * 255.0f;
    y = sigmoidf(z1) * 255.0f;
}

// ---------------- grid pre-conversion: fp32 -> fp16x2 ----------------
__global__ void __launch_bounds__(256) convert_grids(
    const float *__restrict__ g0, const float *__restrict__ g1)
{
    int i = blockIdx.x * 256 + threadIdx.x;
    const float *src = (i < 524288) ? g0 : g1;
    int j = i & 524287;
    float4 v = __ldg((const float4 *)src + j);
    u64 w = (u64)packh2(v.x, v.y) | ((u64)packh2(v.z, v.w) << 32);
    *((u64 *)g_f16 + i) = w;
}

// ---------------- main kernel ----------------
__global__ void __launch_bounds__(128, 5) gridnet_q(
    const float *__restrict__ pos, const float *__restrict__ dir,
    const float *__restrict__ fc_w1, const float *__restrict__ fc_b1,
    const float *__restrict__ fc_w2, const float *__restrict__ fc_b2,
    float *__restrict__ out, int n, int ntiles)
{
    extern __shared__ __align__(16) char smraw[];

    const int tid = threadIdx.x;
    const int warp = tid >> 5, lane = tid & 31;
    const int rowgrp = lane >> 2, sub = lane & 3;  // loader roles (4 lanes/row)
    const int r = lane >> 2, c = lane & 3;         // mma fragment roles

    // ---- stage weights once per CTA: u64-packed (b0,b1) pairs, stride 20 u64
    for (int i = tid; i < 64 * 16; i += 128) {
        int nn = i >> 4, idx = i & 15;  // idx = 4*kt + c
        int kt = idx >> 2, cc = idx & 3;
        int w0k2 = 8 * kt + cc, w1k2 = w0k2 + 4;
        u32 lo = packh2(fc_w1[(2 * w0k2) * 64 + nn], fc_w1[(2 * w0k2 + 1) * 64 + nn]);
        u32 hi = packh2(fc_w1[(2 * w1k2) * 64 + nn], fc_w1[(2 * w1k2 + 1) * 64 + nn]);
        *(u64 *)(smraw + OFFB_W1P + ((u32)(nn * 20 + idx) * 8)) = (u64)lo | ((u64)hi << 32);
    }
    for (int i = tid; i < 16 * 16; i += 128) {
        int nn = i >> 4, idx = i & 15;
        int kt = idx >> 2, cc = idx & 3;
        int w0k2 = 8 * kt + cc, w1k2 = w0k2 + 4;
        u32 lo = packh2(fc_w2[(2 * w0k2) * 16 + nn], fc_w2[(2 * w0k2 + 1) * 16 + nn]);
        u32 hi = packh2(fc_w2[(2 * w1k2) * 16 + nn], fc_w2[(2 * w1k2 + 1) * 16 + nn]);
        *(u64 *)(smraw + OFFB_W2P + ((u32)(nn * 20 + idx) * 8)) = (u64)lo | ((u64)hi << 32);
    }
    if (tid < 64) *(float *)(smraw + OFFB_B1 + tid * 4) = fc_b1[tid];
    if (tid < 16) *(float *)(smraw + OFFB_B2 + tid * 4) = fc_b2[tid];
    __syncthreads();

    const float *sB1 = (const float *)(smraw + OFFB_B1);
    const float *sB2 = (const float *)(smraw + OFFB_B2);
    u32 *sx = (u32 *)(smraw + OFFB_STAGE) + warp * 1024;
    float *sxf = (float *)sx;
    const u32 sx_addr = smem_u32(sx);
    u32 *meta = (u32 *)(smraw + OFFB_META) + warp * 384;  // [32][12]
    const u32 meta_addr = smem_u32(meta);

    // ldmatrix role precompute
    const int mi = lane >> 3, rr = lane & 7;
    const int rotA = ROT(rr);
    const u32 baseA = sx_addr + (u32)(((mi & 1) * 8 + rr) * 128);
    const u32 baseB = baseA + 16 * 128;
    const int khalf = (mi >> 1) * 4;

    // prefetch first tile's coords
    int tile = blockIdx.x;
    float2 pco, dco;
    {
        int pc0 = min(tile * 128 + warp * 32 + lane, n - 1);
        pco = *(const float2 *)(pos + 2 * pc0);
        dco = *(const float2 *)(dir + 2 * pc0);
    }

    for (; tile < ntiles; tile += gridDim.x) {
        const int p = tile * 128 + warp * 32 + lane;
        float2 pcur = pco, dcur = dco;
        int tnext = tile + gridDim.x;
        if (tnext < ntiles) {
            int pcn = min(tnext * 128 + warp * 32 + lane, n - 1);
            pco = *(const float2 *)(pos + 2 * pcn);
            dco = *(const float2 *)(dir + 2 * pcn);
        }

        // ===== owner: encode -> packed u32 corner metadata (cell16 | f16w<<16) =====
        {
            float gx[2], gy[2];
            encode(pcur.x, pcur.y, gx[0], gy[0]);
            encode(dcur.x, dcur.y, gx[1], gy[1]);
#pragma unroll
            for (int g = 0; g < 2; g++) {
                float x = gx[g], y = gy[g];
                int x0 = min((int)x, 255), y0 = min((int)y, 255);
                float xf = x - (float)x0, yf = y - (float)y0;
                int x1 = min(x0 + 1, 255), y1 = min(y0 + 1, 255);
                u32 c0 = (u32)(y0 * 256 + x0);
                u32 c1 = (u32)(y0 * 256 + x1);
                u32 c2 = (u32)(y1 * 256 + x0);
                u32 c3 = (u32)(y1 * 256 + x1);
                float w0 = (1.0f - xf) * (1.0f - yf);
                float w1 = xf * (1.0f - yf);
                float w2 = (1.0f - xf) * yf;
                float w3 = xf * yf;
                u32 m0 = c0 | (packh2(w0, 0.0f) << 16);
                u32 m1 = c1 | (packh2(w1, 0.0f) << 16);
                u32 m2 = c2 | (packh2(w2, 0.0f) << 16);
                u32 m3 = c3 | (packh2(w3, 0.0f) << 16);
                sts128u(meta_addr + (u32)(lane * 48 + g * 16), m0, m1, m2, m3);
            }
        }
        __syncwarp();

        // ===== loader: 4 lanes/row, LDG.128 gather + fp16x2 blend -> rotated stage =====
#pragma unroll 1
        for (int g = 0; g < 2; g++) {
            const char *gbase = (const char *)(g_f16 + (u32)g * 1048576u);
#pragma unroll
            for (int i = 0; i < 4; i++) {
                int row = i * 8 + rowgrp;
                uint4 mg = *(const uint4 *)(meta + row * 12 + g * 4);
                u32 a0 = 0, a1 = 0, a2 = 0, a3 = 0;
#pragma unroll
                for (int cc = 0; cc < 4; cc++) {
                    u32 m = (cc == 0) ? mg.x : (cc == 1) ? mg.y : (cc == 2) ? mg.z : mg.w;
                    u32 wb = prmt_hi2(m);
                    u32 off = (m & 0xFFFFu) << 6;
                    uint4 v = __ldg((const uint4 *)(gbase + off) + sub);
                    a0 = hfma2(v.x, wb, a0);
                    a1 = hfma2(v.y, wb, a1);
                    a2 = hfma2(v.z, wb, a2);
                    a3 = hfma2(v.w, wb, a3);
                }
                int word = row * 32 + ((g * 16 + 4 * sub + ROT(row)) & 31);
                sts128u(sx_addr + (u32)(word * 4), a0, a1, a2, a3);
            }
        }
        __syncwarp();

        // ===== FC1 + FC2 fused: A-frags hoisted once, nt-quarters (d1[16]) =====
        u32 A[32];  // [kt][8]
#pragma unroll
        for (int kt = 0; kt < 4; kt++) {
            u32 wo = (u32)(((8 * kt + khalf + rotA) & 31) * 4);
            ldsm4(A[kt * 8 + 0], A[kt * 8 + 1], A[kt * 8 + 2], A[kt * 8 + 3], baseA + wo);
            ldsm4(A[kt * 8 + 4], A[kt * 8 + 5], A[kt * 8 + 6], A[kt * 8 + 7], baseB + wo);
        }

        float d2[16];
#pragma unroll
        for (int q = 0; q < 16; q++) d2[q] = 0.0f;

#pragma unroll 1
        for (int q = 0; q < 4; q++) {   // nt pair (2q, 2q+1); FC2 k-tile = q
            float d1[16];
#pragma unroll
            for (int z = 0; z < 16; z++) d1[z] = 0.0f;
#pragma unroll
            for (int kt = 0; kt < 4; kt++) {
#pragma unroll
                for (int ntp = 0; ntp < 2; ntp++) {
                    int nt = 2 * q + ntp;
                    u64 bb = *(const u64 *)(smraw + OFFB_W1P +
                                            (u32)(((8 * nt + r) * 20 + 4 * kt + c) * 8));
                    u32 b0 = (u32)bb, b1 = (u32)(bb >> 32);
                    mma_f16(d1 + ntp * 8, A[kt * 8 + 0], A[kt * 8 + 1], A[kt * 8 + 2],
                            A[kt * 8 + 3], b0, b1);
                    mma_f16(d1 + ntp * 8 + 4, A[kt * 8 + 4], A[kt * 8 + 5], A[kt * 8 + 6],
                            A[kt * 8 + 7], b0, b1);
                }
            }
            // FC2 partial: this quarter's D1 = A-frags for k-tile q
            int ntA0 = 2 * q, ntA1 = 2 * q + 1;
            float blo0 = sB1[8 * ntA0 + 2 * c];
            float bhi0 = sB1[8 * ntA0 + 2 * c + 1];
            float blo1 = sB1[8 * ntA1 + 2 * c];
            float bhi1 = sB1[8 * ntA1 + 2 * c + 1];
            u32 a0 = packh2(leaky(d1[0] + blo0), leaky(d1[1] + bhi0));
            u32 a1 = packh2(leaky(d1[2] + blo0), leaky(d1[3] + bhi0));
            u32 a2 = packh2(leaky(d1[8] + blo1), leaky(d1[9] + bhi1));
            u32 a3 = packh2(leaky(d1[10] + blo1), leaky(d1[11] + bhi1));
            u32 a10 = packh2(leaky(d1[4] + blo0), leaky(d1[5] + bhi0));
            u32 a11 = packh2(leaky(d1[6] + blo0), leaky(d1[7] + bhi0));
            u32 a12 = packh2(leaky(d1[12] + blo1), leaky(d1[13] + bhi1));
            u32 a13 = packh2(leaky(d1[14] + blo1), leaky(d1[15] + bhi1));
#pragma unroll
            for (int nt2 = 0; nt2 < 2; nt2++) {
                u64 bb = *(const u64 *)(smraw + OFFB_W2P +
                                        (u32)(((8 * nt2 + r) * 20 + 4 * q + c) * 8));
                u32 b0 = (u32)bb, b1 = (u32)(bb >> 32);
                mma_f16(d2 + nt2 * 8, a0, a1, a2, a3, b0, b1);
                mma_f16(d2 + nt2 * 8 + 4, a10, a11, a12, a13, b0, b1);
            }
        }
        __syncwarp();

        // ===== H2 = leaky(D2 + b2) -> f32 restage (rotated) =====
        {
            int rotH = ROT(r);
#pragma unroll
            for (int nt = 0; nt < 2; nt++) {
                float blo = sB2[8 * nt + 2 * c];
                float bhi = sB2[8 * nt + 2 * c + 1];
                const float *dd = d2 + nt * 8;
                int wo = (8 * nt + 2 * c + rotH) & 31;
                *(u64 *)&sxf[(r) * 32 + wo] = pack2(leaky(dd[0] + blo), leaky(dd[1] + bhi));
                *(u64 *)&sxf[(r + 8) * 32 + wo] = pack2(leaky(dd[2] + blo), leaky(dd[3] + bhi));
                *(u64 *)&sxf[(r + 16) * 32 + wo] = pack2(leaky(dd[4] + blo), leaky(dd[5] + bhi));
                *(u64 *)&sxf[(r + 24) * 32 + wo] = pack2(leaky(dd[6] + blo), leaky(dd[7] + bhi));
            }
        }
        __syncwarp();

        // ===== head: FC3 (16->8, cmem uniform) + FC4 + sigmoid*255 =====
        float a2[16];
        {
            int rotL = ROT(lane);
#pragma unroll
            for (int q = 0; q < 4; q++) {
                float4 v = *(const float4 *)&sxf[lane * 32 + ((4 * q + rotL) & 31)];
                a2[4 * q + 0] = v.x;
                a2[4 * q + 1] = v.y;
                a2[4 * q + 2] = v.z;
                a2[4 * q + 3] = v.w;
            }
        }
        u64 h3[4];
#pragma unroll
        for (int q = 0; q < 4; q++) h3[q] = pack2(cB3[2 * q], cB3[2 * q + 1]);
#pragma unroll
        for (int j = 0; j < 16; j++) {
            float a = a2[j];
            u64 av = pack2(a, a);
            const ulonglong2 *w = (const ulonglong2 *)(cW3 + j * 8);
            ulonglong2 w01 = w[0], w23 = w[1];
            fma2(h3[0], av, w01.x);
            fma2(h3[1], av, w01.y);
            fma2(h3[2], av, w23.x);
            fma2(h3[3], av, w23.y);
        }
        float o0 = cB4[0], o1 = cB4[1], o2 = cB4[2];
#pragma unroll
        for (int q = 0; q < 4; q++) {
            float2 v = unpack2(h3[q]);
            float a0 = leaky(v.x), a1 = leaky(v.y);
            int i0 = 2 * q, i1 = 2 * q + 1;
            o0 = fmaf(a0, cW4[i0 * 3 + 0], o0);
            o1 = fmaf(a0, cW4[i0 * 3 + 1], o1);
            o2 = fmaf(a0, cW4[i0 * 3 + 2], o2);
            o0 = fmaf(a1, cW4[i1 * 3 + 0], o0);
            o1 = fmaf(a1, cW4[i1 * 3 + 1], o1);
            o2 = fmaf(a1, cW4[i1 * 3 + 2], o2);
        }
        o0 = sigmoidf(leaky(o0)) * 255.0f;
        o1 = sigmoidf(leaky(o1)) * 255.0f;
        o2 = sigmoidf(leaky(o2)) * 255.0f;

        if (p < n) {
            out[p * 3 + 0] = o0;
            out[p * 3 + 1] = o1;
            out[p * 3 + 2] = o2;
        }
        __syncwarp();  // stage/meta reuse across tiles
    }
}

extern "C" void kernel_launch(void *const *d_in, const int *in_sizes, int n_in,
                              void *d_out, int out_size)
{
    const float *pos = (const float *)d_in[0];
    const float *dir = (const float *)d_in[1];
    const float *pos_grid = (const float *)d_in[2];
    const float *dir_grid = (const float *)d_in[3];

    cudaMemcpyToSymbolAsync(cEnc, d_in[4], 8 * sizeof(float), 0, cudaMemcpyDeviceToDevice, 0);
    cudaMemcpyToSymbolAsync(cEnc, d_in[5], 4 * sizeof(float), 8 * sizeof(float), cudaMemcpyDeviceToDevice, 0);
    cudaMemcpyToSymbolAsync(cEnc, d_in[6], 12 * sizeof(float), 12 * sizeof(float), cudaMemcpyDeviceToDevice, 0);
    cudaMemcpyToSymbolAsync(cEnc, d_in[7], 3 * sizeof(float), 24 * sizeof(float), cudaMemcpyDeviceToDevice, 0);
    cudaMemcpyToSymbolAsync(cW3, d_in[12], 16 * 8 * sizeof(float), 0, cudaMemcpyDeviceToDevice, 0);
    cudaMemcpyToSymbolAsync(cB3, d_in[13], 8 * sizeof(float), 0, cudaMemcpyDeviceToDevice, 0);
    cudaMemcpyToSymbolAsync(cW4, d_in[14], 8 * 3 * sizeof(float), 0, cudaMemcpyDeviceToDevice, 0);
    cudaMemcpyToSymbolAsync(cB4, d_in[15], 3 * sizeof(float), 0, cudaMemcpyDeviceToDevice, 0);

    convert_grids<<<4096, 256>>>(pos_grid, dir_grid);

    cudaFuncSetAttribute(gridnet_q, cudaFuncAttributeMaxDynamicSharedMemorySize, DYN_BYTES);

    float *out = (float *)d_out;
    int n = in_sizes[0] / 2;
    int ntiles = (n + 127) / 128;
    int blocks = 148 * 5;
    if (blocks > ntiles) blocks = ntiles;
    gridnet_q<<<blocks, 128, DYN_BYTES>>>(
        pos, dir,
        (const float *)d_in[8], (const float *)d_in[9],
        (const float *)d_in[10], (const float *)d_in[11],
        out, n, ntiles);
}